// round 13
// baseline (speedup 1.0000x reference)
#include <cuda_runtime.h>
#include <cuda_fp16.h>
#include <math.h>
#include <stdint.h>

// Problem shapes
#define Bn  256
#define Kn  64
#define Dn  1024
#define KD  4096                // MLP1 K dim = 4*Dn
#define Hn  4
#define NLn 3

// Output layout in d_out (fp32): logits (B*NL), alpha (B*H*K), head_weights (B*H)
#define ALPHA_OFF 768
#define HW_OFF    (768 + Bn*Hn*Kn)

// HMMA GEMM tiling: CTA 128x128, warp tile 32x64, 8 warps, 2 CTAs/SM
#define TCM 128
#define TCN 128
#define KC  64                  // K elems per chunk (64 fp16 = 128B row)
#define NCHUNK (Dn / KC)        // 16
#define NET    (Dn / TCN)       // 8 e-tiles
#define NTHREADS 256
#define NSTAGE 3

// MLP1 split-k
#define SPLITK 16
#define KSPAN  (KD / SPLITK)    // 256
#define NCHUNK_M (KSPAN / KC)   // 4

typedef unsigned long long u64;

// -------- scratch (static device globals; no allocation allowed) --------
__device__ float g_wcsum[Hn * Dn];
__device__ float g_upart[NET * Bn * Hn * Kn];       // 2 MB
__device__ float g_hidpart[SPLITK * Bn * Dn];       // 16 MB
// fp16 operands (single-rounded)
__device__ __half g_Ef[Bn * Kn * Dn];    // 32 MB
__device__ __half g_Wt[Hn * Dn * Dn];    // 8 MB  (transposed: [h][e][d])
__device__ __half g_w1h[Dn * KD];        // 8 MB  (w1 fp16, [N=1024][K=4096])
__device__ __half g_feath[Bn * KD];      // 2 MB  (features fp16, [256][4096])

// -------- helpers --------
__device__ __forceinline__ uint32_t smem_u32(const void* p) {
    uint32_t a;
    asm("{ .reg .u64 t; cvta.to.shared.u64 t, %1; cvt.u32.u64 %0, t; }" : "=r"(a) : "l"(p));
    return a;
}
__device__ __forceinline__ float tanhfast(float x) {
    float y; asm("tanh.approx.f32 %0, %1;" : "=f"(y) : "f"(x)); return y;
}
#define SWZ128(o) ((o) ^ (((o) >> 3) & 0x70))

__device__ __forceinline__ void cp16(uint32_t saddr, const void* gptr) {
    asm volatile("cp.async.cg.shared.global [%0], [%1], 16;"
                 :: "r"(saddr), "l"(__cvta_generic_to_global(gptr)) : "memory");
}
#define CP_COMMIT() asm volatile("cp.async.commit_group;" ::: "memory")
#define CP_WAIT(n)  asm volatile("cp.async.wait_group %0;" :: "n"(n) : "memory")

#define LDSM_X4(r0, r1, r2, r3, addr) \
    asm volatile("ldmatrix.sync.aligned.m8n8.x4.shared.b16 {%0,%1,%2,%3}, [%4];" \
                 : "=r"(r0), "=r"(r1), "=r"(r2), "=r"(r3) : "r"(addr))

#define MMA_F16(c, a, b) \
    asm volatile("mma.sync.aligned.m16n8k16.row.col.f32.f16.f16.f32 " \
                 "{%0,%1,%2,%3}, {%4,%5,%6,%7}, {%8,%9}, {%0,%1,%2,%3};" \
                 : "+f"((c)[0]), "+f"((c)[1]), "+f"((c)[2]), "+f"((c)[3]) \
                 : "r"((a)[0]), "r"((a)[1]), "r"((a)[2]), "r"((a)[3]), \
                   "r"((b)[0]), "r"((b)[1]))

// smem stage layout: A(16KB) + B(16KB) = 32KB per stage
#define OFF_A   0
#define OFF_B   16384
#define STAGE_BYTES 32768
#define SM_EXTRA (NSTAGE * STAGE_BYTES)               // epilogue arrays beyond stages
#define SMEM_TOTAL (NSTAGE * STAGE_BYTES + 4096)      // 102400 -> 2 CTAs/SM

// -------- K0: fused preprocessing (cvtE | cvtW | wcsum | cvtW1) ----
#define NBLK_E  (Bn*Kn*Dn/4/256)      // 16384
#define NBLK_W  ((Dn/32)*(Dn/32)*Hn)  // 4096
#define NBLK_S  (Hn*Dn*32/256)        // 512
#define NBLK_W1 (Dn*KD/4/256)         // 4096
__global__ void k_prep(const float* __restrict__ e, const float* __restrict__ W,
                       const float* __restrict__ W_c, const float* __restrict__ w1) {
    __shared__ float t[32][33];
    const int bx = blockIdx.x;
    const int tid = threadIdx.x;
    if (bx < NBLK_E) {
        size_t i = (size_t)bx * 256 + tid;   // over float4s
        float4 x = ((const float4*)e)[i];
        __half h0 = __float2half_rn(x.x), h1 = __float2half_rn(x.y);
        __half h2 = __float2half_rn(x.z), h3 = __float2half_rn(x.w);
        ((__half2*)g_Ef)[2*i    ] = __halves2half2(h0, h1);
        ((__half2*)g_Ef)[2*i + 1] = __halves2half2(h2, h3);
    } else if (bx < NBLK_E + NBLK_W) {
        const int b  = bx - NBLK_E;
        const int h  = b >> 10;
        const int dB = ((b & 1023) >> 5) * 32;
        const int eB = (b & 31) * 32;
        const int lx = tid & 31, ly = tid >> 5;  // 32 x 8
        #pragma unroll
        for (int r = 0; r < 4; ++r)
            t[ly + 8*r][lx] = W[((size_t)h*Dn + dB + ly + 8*r) * Dn + eB + lx];
        __syncthreads();
        #pragma unroll
        for (int r = 0; r < 4; ++r) {
            float x = t[lx][ly + 8*r];
            size_t oi = ((size_t)h*Dn + eB + ly + 8*r) * Dn + dB + lx;
            g_Wt[oi] = __float2half_rn(x);
        }
    } else if (bx < NBLK_E + NBLK_W + NBLK_S) {
        int warp = (((bx - NBLK_E - NBLK_W) << 8) + tid) >> 5;
        int lane = tid & 31;
        const float* p = W_c + (size_t)warp * Dn;
        float s = 0.f;
        #pragma unroll 8
        for (int j = lane; j < Dn; j += 32) s += p[j];
        #pragma unroll
        for (int o = 16; o; o >>= 1) s += __shfl_down_sync(0xffffffffu, s, o);
        if (!lane) g_wcsum[warp] = s;
    } else {
        size_t i = (size_t)(bx - NBLK_E - NBLK_W - NBLK_S) * 256 + tid;
        float4 x = ((const float4*)w1)[i];
        __half h0 = __float2half_rn(x.x), h1 = __float2half_rn(x.y);
        __half h2 = __float2half_rn(x.z), h3 = __float2half_rn(x.w);
        ((__half2*)g_w1h)[2*i    ] = __halves2half2(h0, h1);
        ((__half2*)g_w1h)[2*i + 1] = __halves2half2(h2, h3);
    }
}

// -------- K2: HMMA fused  P = E @ Wt^T (fp16);  u = sum_e tanh(cp+P)*v ----
__global__ void __launch_bounds__(NTHREADS, 2)
k_attn_mma(const float* __restrict__ c_out, const float* __restrict__ v)
{
    extern __shared__ char smem[];
    const uint32_t sb = smem_u32(smem);
    const int tid   = threadIdx.x;
    const int wid   = tid >> 5;
    const int lane  = tid & 31;
    const int warpM = wid >> 1;
    const int warpN = wid & 1;

    const int et      = blockIdx.x;
    const int rowBase = blockIdx.y * TCM;
    const int h       = blockIdx.z;
    const int eBase   = et * TCN;

    const __half* Ap = g_Ef + (size_t)rowBase * Dn;
    const __half* Bp = g_Wt + ((size_t)h * Dn + eBase) * Dn;

    float* s_cce0 = (float*)(smem + SM_EXTRA);
    float* s_cce1 = s_cce0 + TCN;
    float* s_vv   = s_cce1 + TCN;
    float* s_red  = s_vv + TCN;

    const int b0 = rowBase >> 6;
    {
        int e0 = eBase + (tid & 127);
        float wc0 = g_wcsum[h * Dn + e0];
        if (tid < 128) {
            s_cce0[tid] = c_out[b0 * Dn + e0] * wc0;
            s_vv[tid]   = v[h * Dn + e0];
        } else {
            s_cce1[tid - 128] = c_out[(b0 + 1) * Dn + e0] * wc0;
        }
    }

    int arow[4], ac16[4]; uint32_t aso[4];
    #pragma unroll
    for (int i = 0; i < 4; ++i) {
        int seg = tid + i * NTHREADS;
        arow[i] = seg >> 3; ac16[i] = seg & 7;
        aso[i] = SWZ128((uint32_t)(arow[i] * 128 + ac16[i] * 16));
    }

    float acc[2][8][4];
    #pragma unroll
    for (int mt = 0; mt < 2; ++mt)
        #pragma unroll
        for (int nt = 0; nt < 8; ++nt)
            #pragma unroll
            for (int j = 0; j < 4; ++j) acc[mt][nt][j] = 0.f;

    const uint32_t aRowB = (uint32_t)((warpM * 32 + (lane & 15)) * 128);
    const uint32_t bRowB = (uint32_t)((warpN * 64 + (lane & 15)) * 128);
    const uint32_t colSel = (uint32_t)((lane >> 4) * 16);

    #pragma unroll
    for (int pc = 0; pc < 2; ++pc) {
        const uint32_t st = sb + pc * STAGE_BYTES;
        const int dB = pc * KC;
        #pragma unroll
        for (int i = 0; i < 4; ++i) {
            cp16(st + OFF_A + aso[i], Ap + (size_t)arow[i] * Dn + dB + ac16[i] * 8);
            cp16(st + OFF_B + aso[i], Bp + (size_t)arow[i] * Dn + dB + ac16[i] * 8);
        }
        CP_COMMIT();
    }

    int stage = 0;
    for (int c = 0; c < NCHUNK; ++c) {
        if (c + 2 < NCHUNK) { CP_WAIT(1); } else { CP_WAIT(0); }
        __syncthreads();

        if (c + 2 < NCHUNK) {
            int ns = stage + 2; if (ns >= NSTAGE) ns -= NSTAGE;
            const uint32_t stn = sb + ns * STAGE_BYTES;
            const int dB = (c + 2) * KC;
            #pragma unroll
            for (int i = 0; i < 4; ++i) {
                cp16(stn + OFF_A + aso[i], Ap + (size_t)arow[i] * Dn + dB + ac16[i] * 8);
                cp16(stn + OFF_B + aso[i], Bp + (size_t)arow[i] * Dn + dB + ac16[i] * 8);
            }
            CP_COMMIT();
        }

        const uint32_t st = sb + stage * STAGE_BYTES;
        #pragma unroll
        for (int ks = 0; ks < KC / 16; ++ks) {
            const uint32_t kcol = ks * 32 + colSel;
            uint32_t af[2][4];
            #pragma unroll
            for (int mt = 0; mt < 2; ++mt) {
                uint32_t off = SWZ128(aRowB + (uint32_t)(mt * 16 * 128) + kcol);
                LDSM_X4(af[mt][0], af[mt][1], af[mt][2], af[mt][3], st + OFF_A + off);
            }
            uint32_t bf[8][2];
            #pragma unroll
            for (int p = 0; p < 4; ++p) {
                uint32_t off = SWZ128(bRowB + (uint32_t)(p * 16 * 128) + kcol);
                uint32_t r0, r1, r2, r3;
                LDSM_X4(r0, r1, r2, r3, st + OFF_B + off);
                bf[2*p][0] = r0; bf[2*p][1] = r2;
                bf[2*p+1][0] = r1; bf[2*p+1][1] = r3;
            }
            #pragma unroll
            for (int mt = 0; mt < 2; ++mt)
                #pragma unroll
                for (int nt = 0; nt < 8; ++nt)
                    MMA_F16(acc[mt][nt], af[mt], bf[nt]);
        }
        if (++stage == NSTAGE) stage = 0;
    }

    const int gRow = lane >> 2;
    const int c2   = (lane & 3) * 2;
    const float* cce = (warpM >= 2) ? s_cce1 : s_cce0;

    #pragma unroll
    for (int mt = 0; mt < 2; ++mt) {
        #pragma unroll
        for (int h2 = 0; h2 < 2; ++h2) {
            float p = 0.f;
            #pragma unroll
            for (int nt = 0; nt < 8; ++nt) {
                int e0 = warpN * 64 + nt * 8 + c2;
                float v0 = acc[mt][nt][h2 * 2 + 0];
                float v1 = acc[mt][nt][h2 * 2 + 1];
                p += tanhfast(v0 + cce[e0    ]) * s_vv[e0    ];
                p += tanhfast(v1 + cce[e0 + 1]) * s_vv[e0 + 1];
            }
            p += __shfl_xor_sync(0xffffffffu, p, 1);
            p += __shfl_xor_sync(0xffffffffu, p, 2);
            if ((lane & 3) == 0) {
                int lrow2 = warpM * 32 + mt * 16 + h2 * 8 + gRow;
                s_red[lrow2 * 2 + warpN] = p;
            }
        }
    }
    __syncthreads();

    if (tid < 128) {
        float s = s_red[tid*2] + s_red[tid*2+1];
        int rg = rowBase + tid;
        int bb = rg >> 6, kk = rg & 63;
        g_upart[et * (Bn * Hn * Kn) + ((bb * Hn + h) << 6) + kk] = s;
    }
}

// -------- K4: FUSED softmax + e_att_heads + gate + head_wts + feat ----
// grid: Bn blocks x 512 threads; each thread owns a consecutive d-pair (half2).
__global__ void __launch_bounds__(512)
k_fuse(const int* __restrict__ mask, const float* __restrict__ c_out,
       const float* __restrict__ gate_w, const float* __restrict__ gate_b,
       float* __restrict__ out)
{
    const int b = blockIdx.x, tid = threadIdx.x;
    const int lane = tid & 31, wid = tid >> 5;   // 16 warps

    __shared__ float red[256];
    __shared__ float sal[256];          // alpha [h][k]
    __shared__ float gred[16][5];
    __shared__ float shw[4];

    // ---- softmax over k within each h (4 groups of 64 threads) ----
    float s = 0.f;
    if (tid < 256) {
        const int hh = tid >> 6, kk = tid & 63;
        #pragma unroll
        for (int nt = 0; nt < NET; ++nt)
            s += g_upart[nt * (Bn*Hn*Kn) + ((b * Hn + hh) << 6) + kk];
        if (mask[b * Kn + kk] == 0) s = __int_as_float(0xff800000);
        red[tid] = s;
    }
    __syncthreads();
    #pragma unroll
    for (int o = 32; o; o >>= 1) {
        if (tid < 256 && (tid & 63) < o) red[tid] = fmaxf(red[tid], red[tid + o]);
        __syncthreads();
    }
    float ex = 0.f;
    if (tid < 256) ex = __expf(s - red[(tid >> 6) << 6]);
    __syncthreads();
    if (tid < 256) red[tid] = ex;
    __syncthreads();
    #pragma unroll
    for (int o = 32; o; o >>= 1) {
        if (tid < 256 && (tid & 63) < o) red[tid] += red[tid + o];
        __syncthreads();
    }
    if (tid < 256) {
        float al = ex / red[(tid >> 6) << 6];
        sal[tid] = al;
        out[ALPHA_OFF + b * (Hn*Kn) + tid] = al;
    }
    __syncthreads();

    // ---- e_att_heads for d-pair (half2 loads, 128B warp transactions) ----
    const __half2* ep2 = (const __half2*)(g_Ef + (size_t)b * Kn * Dn) + tid;
    float2 A0 = {0.f, 0.f}, A1 = {0.f, 0.f}, A2 = {0.f, 0.f}, A3 = {0.f, 0.f};
    #pragma unroll 8
    for (int k = 0; k < Kn; ++k) {
        float2 ev = __half22float2(ep2[k * (Dn/2)]);
        float s0 = sal[k], s1 = sal[64+k], s2 = sal[128+k], s3 = sal[192+k];
        A0.x = fmaf(s0, ev.x, A0.x); A0.y = fmaf(s0, ev.y, A0.y);
        A1.x = fmaf(s1, ev.x, A1.x); A1.y = fmaf(s1, ev.y, A1.y);
        A2.x = fmaf(s2, ev.x, A2.x); A2.y = fmaf(s2, ev.y, A2.y);
        A3.x = fmaf(s3, ev.x, A3.x); A3.y = fmaf(s3, ev.y, A3.y);
    }

    // ---- gate: per-thread pair partials; warp + cross-warp reduce ----
    float2 cv  = ((const float2*)(c_out + (size_t)b * Dn))[tid];
    float2 gwc = ((const float2*)gate_w)[tid];
    float2 gwe = ((const float2*)(gate_w + Dn))[tid];
    float pv[5];
    pv[0] = cv.x * gwc.x + cv.y * gwc.y;
    pv[1] = A0.x * gwe.x + A0.y * gwe.y;
    pv[2] = A1.x * gwe.x + A1.y * gwe.y;
    pv[3] = A2.x * gwe.x + A2.y * gwe.y;
    pv[4] = A3.x * gwe.x + A3.y * gwe.y;
    #pragma unroll
    for (int i = 0; i < 5; ++i) {
        float x = pv[i];
        #pragma unroll
        for (int o = 16; o; o >>= 1) x += __shfl_xor_sync(0xffffffffu, x, o);
        if (!lane) gred[wid][i] = x;
    }
    __syncthreads();
    if (wid == 0) {
        #pragma unroll
        for (int i = 0; i < 5; ++i) {
            float x = (lane < 16) ? gred[lane][i] : 0.f;
            #pragma unroll
            for (int o = 8; o; o >>= 1) x += __shfl_xor_sync(0xffffffffu, x, o);
            if (!lane) gred[0][i] = x;
        }
        if (!lane) {
            float gb = gate_b[0];
            float g0 = gred[0][0] + gred[0][1] + gb, g1 = gred[0][0] + gred[0][2] + gb;
            float g2 = gred[0][0] + gred[0][3] + gb, g3 = gred[0][0] + gred[0][4] + gb;
            float mx = fmaxf(fmaxf(g0, g1), fmaxf(g2, g3));
            float e0 = __expf(g0 - mx), e1 = __expf(g1 - mx);
            float e2 = __expf(g2 - mx), e3 = __expf(g3 - mx);
            float inv = 1.f / (e0 + e1 + e2 + e3);
            shw[0] = e0*inv; shw[1] = e1*inv; shw[2] = e2*inv; shw[3] = e3*inv;
            out[HW_OFF + b*Hn + 0] = shw[0]; out[HW_OFF + b*Hn + 1] = shw[1];
            out[HW_OFF + b*Hn + 2] = shw[2]; out[HW_OFF + b*Hn + 3] = shw[3];
        }
    }
    __syncthreads();

    // ---- feature vector (fp16, half2 stores) ----
    float hw0 = shw[0], hw1 = shw[1], hw2 = shw[2], hw3 = shw[3];
    float2 ea;
    ea.x = hw0*A0.x + hw1*A1.x + hw2*A2.x + hw3*A3.x;
    ea.y = hw0*A0.y + hw1*A1.y + hw2*A2.y + hw3*A3.y;
    __half2* fb = (__half2*)(g_feath + (size_t)b * KD);
    fb[            tid] = __floats2half2_rn(cv.x, cv.y);
    fb[ (Dn/2)   + tid] = __floats2half2_rn(ea.x, ea.y);
    fb[2*(Dn/2)  + tid] = __floats2half2_rn(fabsf(cv.x - ea.x), fabsf(cv.y - ea.y));
    fb[3*(Dn/2)  + tid] = __floats2half2_rn(cv.x * ea.x, cv.y * ea.y);
}

// -------- K7: hid_part = feat @ w1.T via HMMA fp16 (split-k=16) --------
__global__ void __launch_bounds__(NTHREADS, 2)
k_mlp1() {
    extern __shared__ char smem[];
    const uint32_t sb = smem_u32(smem);
    const int tid   = threadIdx.x;
    const int wid   = tid >> 5;
    const int lane  = tid & 31;
    const int warpM = wid >> 1;
    const int warpN = wid & 1;

    const int oBase   = blockIdx.x * TCN;
    const int rowBase = blockIdx.y * TCM;
    const int z       = blockIdx.z;
    const int kBase   = z * KSPAN;

    const __half* Ap = g_feath + (size_t)rowBase * KD + kBase;
    const __half* Bp = g_w1h   + (size_t)oBase * KD + kBase;

    int arow[4], ac16[4]; uint32_t aso[4];
    #pragma unroll
    for (int i = 0; i < 4; ++i) {
        int seg = tid + i * NTHREADS;
        arow[i] = seg >> 3; ac16[i] = seg & 7;
        aso[i] = SWZ128((uint32_t)(arow[i] * 128 + ac16[i] * 16));
    }

    float acc[2][8][4];
    #pragma unroll
    for (int mt = 0; mt < 2; ++mt)
        #pragma unroll
        for (int nt = 0; nt < 8; ++nt)
            #pragma unroll
            for (int j = 0; j < 4; ++j) acc[mt][nt][j] = 0.f;

    const uint32_t aRowB = (uint32_t)((warpM * 32 + (lane & 15)) * 128);
    const uint32_t bRowB = (uint32_t)((warpN * 64 + (lane & 15)) * 128);
    const uint32_t colSel = (uint32_t)((lane >> 4) * 16);

    #pragma unroll
    for (int pc = 0; pc < 2; ++pc) {
        const uint32_t st = sb + pc * STAGE_BYTES;
        const int dB = pc * KC;
        #pragma unroll
        for (int i = 0; i < 4; ++i) {
            cp16(st + OFF_A + aso[i], Ap + (size_t)arow[i] * KD + dB + ac16[i] * 8);
            cp16(st + OFF_B + aso[i], Bp + (size_t)arow[i] * KD + dB + ac16[i] * 8);
        }
        CP_COMMIT();
    }

    int stage = 0;
    for (int c = 0; c < NCHUNK_M; ++c) {
        if (c + 2 < NCHUNK_M) { CP_WAIT(1); } else { CP_WAIT(0); }
        __syncthreads();

        if (c + 2 < NCHUNK_M) {
            int ns = stage + 2; if (ns >= NSTAGE) ns -= NSTAGE;
            const uint32_t stn = sb + ns * STAGE_BYTES;
            const int dB = (c + 2) * KC;
            #pragma unroll
            for (int i = 0; i < 4; ++i) {
                cp16(stn + OFF_A + aso[i], Ap + (size_t)arow[i] * KD + dB + ac16[i] * 8);
                cp16(stn + OFF_B + aso[i], Bp + (size_t)arow[i] * KD + dB + ac16[i] * 8);
            }
            CP_COMMIT();
        }

        const uint32_t st = sb + stage * STAGE_BYTES;
        #pragma unroll
        for (int ks = 0; ks < KC / 16; ++ks) {
            const uint32_t kcol = ks * 32 + colSel;
            uint32_t af[2][4];
            #pragma unroll
            for (int mt = 0; mt < 2; ++mt) {
                uint32_t off = SWZ128(aRowB + (uint32_t)(mt * 16 * 128) + kcol);
                LDSM_X4(af[mt][0], af[mt][1], af[mt][2], af[mt][3], st + OFF_A + off);
            }
            uint32_t bf[8][2];
            #pragma unroll
            for (int p = 0; p < 4; ++p) {
                uint32_t off = SWZ128(bRowB + (uint32_t)(p * 16 * 128) + kcol);
                uint32_t r0, r1, r2, r3;
                LDSM_X4(r0, r1, r2, r3, st + OFF_B + off);
                bf[2*p][0] = r0; bf[2*p][1] = r2;
                bf[2*p+1][0] = r1; bf[2*p+1][1] = r3;
            }
            #pragma unroll
            for (int mt = 0; mt < 2; ++mt)
                #pragma unroll
                for (int nt = 0; nt < 8; ++nt)
                    MMA_F16(acc[mt][nt], af[mt], bf[nt]);
        }
        if (++stage == NSTAGE) stage = 0;
    }

    float* slab = g_hidpart + (size_t)z * (Bn * Dn);
    const int gRow = lane >> 2;
    const int gCol = (lane & 3) * 2;
    #pragma unroll
    for (int mt = 0; mt < 2; ++mt)
        #pragma unroll
        for (int h2 = 0; h2 < 2; ++h2) {
            int row = rowBase + warpM * 32 + mt * 16 + h2 * 8 + gRow;
            #pragma unroll
            for (int nt = 0; nt < 8; ++nt) {
                int col = oBase + warpN * 64 + nt * 8 + gCol;
                float2 val = make_float2(acc[mt][nt][h2*2], acc[mt][nt][h2*2+1]);
                *(float2*)&slab[(size_t)row * Dn + col] = val;
            }
        }
}

// -------- K8: relu(sum hid_parts + b1) @ w2.T + b2 -> logits --------
__global__ void k_logits(const float* __restrict__ b1, const float* __restrict__ w2,
                         const float* __restrict__ b2, float* __restrict__ out) {
    const int b = blockIdx.x, tid = threadIdx.x;
    float a0 = 0.f, a1 = 0.f, a2 = 0.f;
    for (int d = tid; d < Dn; d += 128) {
        float hp = b1[d];
        #pragma unroll
        for (int zz = 0; zz < SPLITK; ++zz)
            hp += g_hidpart[(size_t)zz * (Bn*Dn) + b*Dn + d];
        hp = fmaxf(hp, 0.f);
        a0 = fmaf(hp, w2[        d], a0);
        a1 = fmaf(hp, w2[  Dn + d], a1);
        a2 = fmaf(hp, w2[2*Dn + d], a2);
    }
    __shared__ float red[128];
    __shared__ float vals[3];
    float pv[3] = {a0, a1, a2};
    for (int i = 0; i < 3; ++i) {
        red[tid] = pv[i]; __syncthreads();
        #pragma unroll
        for (int o = 64; o; o >>= 1) { if (tid < o) red[tid] += red[tid+o]; __syncthreads(); }
        if (!tid) vals[i] = red[0];
        __syncthreads();
    }
    if (!tid) {
        out[b*NLn + 0] = vals[0] + b2[0];
        out[b*NLn + 1] = vals[1] + b2[1];
        out[b*NLn + 2] = vals[2] + b2[2];
    }
}

extern "C" void kernel_launch(void* const* d_in, const int* in_sizes, int n_in,
                              void* d_out, int out_size) {
    const float* c_out  = (const float*)d_in[0];
    const float* e_emb  = (const float*)d_in[1];
    const int*   emask  = (const int*)  d_in[2];
    const float* W_c    = (const float*)d_in[3];
    const float* W_e    = (const float*)d_in[4];
    const float* v      = (const float*)d_in[5];
    const float* gate_w = (const float*)d_in[6];
    const float* gate_b = (const float*)d_in[7];
    const float* w1     = (const float*)d_in[8];
    const float* b1     = (const float*)d_in[9];
    const float* w2     = (const float*)d_in[10];
    const float* b2     = (const float*)d_in[11];
    float* out = (float*)d_out;

    cudaFuncSetAttribute(k_attn_mma, cudaFuncAttributeMaxDynamicSharedMemorySize, SMEM_TOTAL);
    cudaFuncSetAttribute(k_mlp1, cudaFuncAttributeMaxDynamicSharedMemorySize, SMEM_TOTAL);

    k_prep<<<NBLK_E + NBLK_W + NBLK_S + NBLK_W1, 256>>>(e_emb, W_e, W_c, w1);
    k_attn_mma<<<dim3(NET, (Bn*Kn)/TCM, Hn), NTHREADS, SMEM_TOTAL>>>(c_out, v);
    k_fuse<<<Bn, 512>>>(emask, c_out, gate_w, gate_b, out);
    k_mlp1<<<dim3(Dn/TCN, Bn/TCM, SPLITK), NTHREADS, SMEM_TOTAL>>>();
    k_logits<<<Bn, 128>>>(b1, w2, b2, out);
}

// round 14
// speedup vs baseline: 1.0173x; 1.0173x over previous
#include <cuda_runtime.h>
#include <cuda_fp16.h>
#include <math.h>
#include <stdint.h>

// Problem shapes
#define Bn  256
#define Kn  64
#define Dn  1024
#define KD  4096                // MLP1 K dim = 4*Dn
#define Hn  4
#define NLn 3

// Output layout in d_out (fp32): logits (B*NL), alpha (B*H*K), head_weights (B*H)
#define ALPHA_OFF 768
#define HW_OFF    (768 + Bn*Hn*Kn)

// HMMA GEMM tiling: CTA 128x128, warp tile 32x64, 8 warps, 2 CTAs/SM
#define TCM 128
#define TCN 128
#define KC  64                  // K elems per chunk (64 fp16 = 128B row)
#define NCHUNK (Dn / KC)        // 16
#define NET    (Dn / TCN)       // 8 e-tiles
#define NTHREADS 256
#define NSTAGE 3

// MLP1: CTA 128x64, split-k=8 -> 256 CTAs, 8-chunk pipeline
#define SPLITK 8
#define KSPAN  (KD / SPLITK)    // 512
#define NCHUNK_M (KSPAN / KC)   // 8
#define TCN_M 64

typedef unsigned long long u64;

// -------- scratch (static device globals; no allocation allowed) --------
__device__ float g_wcsum[Hn * Dn];
__device__ float g_upart[NET * Bn * Hn * Kn];       // 2 MB
__device__ float g_hidpart[SPLITK * Bn * Dn];       // 8 MB
// fp16 operands (single-rounded)
__device__ __half g_Ef[Bn * Kn * Dn];    // 32 MB
__device__ __half g_Wt[Hn * Dn * Dn];    // 8 MB  (transposed: [h][e][d])
__device__ __half g_w1h[Dn * KD];        // 8 MB  (w1 fp16, [N=1024][K=4096])
__device__ __half g_feath[Bn * KD];      // 2 MB  (features fp16, [256][4096])

// -------- helpers --------
__device__ __forceinline__ uint32_t smem_u32(const void* p) {
    uint32_t a;
    asm("{ .reg .u64 t; cvta.to.shared.u64 t, %1; cvt.u32.u64 %0, t; }" : "=r"(a) : "l"(p));
    return a;
}
__device__ __forceinline__ float tanhfast(float x) {
    float y; asm("tanh.approx.f32 %0, %1;" : "=f"(y) : "f"(x)); return y;
}
#define SWZ128(o) ((o) ^ (((o) >> 3) & 0x70))

__device__ __forceinline__ void cp16(uint32_t saddr, const void* gptr) {
    asm volatile("cp.async.cg.shared.global [%0], [%1], 16;"
                 :: "r"(saddr), "l"(__cvta_generic_to_global(gptr)) : "memory");
}
#define CP_COMMIT() asm volatile("cp.async.commit_group;" ::: "memory")
#define CP_WAIT(n)  asm volatile("cp.async.wait_group %0;" :: "n"(n) : "memory")

#define LDSM_X4(r0, r1, r2, r3, addr) \
    asm volatile("ldmatrix.sync.aligned.m8n8.x4.shared.b16 {%0,%1,%2,%3}, [%4];" \
                 : "=r"(r0), "=r"(r1), "=r"(r2), "=r"(r3) : "r"(addr))

#define MMA_F16(c, a, b) \
    asm volatile("mma.sync.aligned.m16n8k16.row.col.f32.f16.f16.f32 " \
                 "{%0,%1,%2,%3}, {%4,%5,%6,%7}, {%8,%9}, {%0,%1,%2,%3};" \
                 : "+f"((c)[0]), "+f"((c)[1]), "+f"((c)[2]), "+f"((c)[3]) \
                 : "r"((a)[0]), "r"((a)[1]), "r"((a)[2]), "r"((a)[3]), \
                   "r"((b)[0]), "r"((b)[1]))

// attn smem stage layout: A(16KB) + B(16KB) = 32KB per stage
#define OFF_A   0
#define OFF_B   16384
#define STAGE_BYTES 32768
#define SM_EXTRA (NSTAGE * STAGE_BYTES)
#define SMEM_TOTAL (NSTAGE * STAGE_BYTES + 4096)      // 102400 -> 2 CTAs/SM

// mlp1 smem stage layout: A(16KB) + B(8KB) = 24KB per stage
#define OFF_B_M  16384
#define STAGE_M  24576
#define SMEM_TOTAL_M (NSTAGE * STAGE_M)               // 73728 -> 2 CTAs/SM

// -------- K0: fused preprocessing (cvtE | cvtW | wcsum | cvtW1) ----
#define NBLK_E  (Bn*Kn*Dn/4/256)      // 16384
#define NBLK_W  ((Dn/32)*(Dn/32)*Hn)  // 4096
#define NBLK_S  (Hn*Dn*32/256)        // 512
#define NBLK_W1 (Dn*KD/4/256)         // 4096
__global__ void k_prep(const float* __restrict__ e, const float* __restrict__ W,
                       const float* __restrict__ W_c, const float* __restrict__ w1) {
    __shared__ float t[32][33];
    const int bx = blockIdx.x;
    const int tid = threadIdx.x;
    if (bx < NBLK_E) {
        size_t i = (size_t)bx * 256 + tid;   // over float4s
        float4 x = ((const float4*)e)[i];
        __half h0 = __float2half_rn(x.x), h1 = __float2half_rn(x.y);
        __half h2 = __float2half_rn(x.z), h3 = __float2half_rn(x.w);
        ((__half2*)g_Ef)[2*i    ] = __halves2half2(h0, h1);
        ((__half2*)g_Ef)[2*i + 1] = __halves2half2(h2, h3);
    } else if (bx < NBLK_E + NBLK_W) {
        const int b  = bx - NBLK_E;
        const int h  = b >> 10;
        const int dB = ((b & 1023) >> 5) * 32;
        const int eB = (b & 31) * 32;
        const int lx = tid & 31, ly = tid >> 5;  // 32 x 8
        #pragma unroll
        for (int r = 0; r < 4; ++r)
            t[ly + 8*r][lx] = W[((size_t)h*Dn + dB + ly + 8*r) * Dn + eB + lx];
        __syncthreads();
        #pragma unroll
        for (int r = 0; r < 4; ++r) {
            float x = t[lx][ly + 8*r];
            size_t oi = ((size_t)h*Dn + eB + ly + 8*r) * Dn + dB + lx;
            g_Wt[oi] = __float2half_rn(x);
        }
    } else if (bx < NBLK_E + NBLK_W + NBLK_S) {
        int warp = (((bx - NBLK_E - NBLK_W) << 8) + tid) >> 5;
        int lane = tid & 31;
        const float* p = W_c + (size_t)warp * Dn;
        float s = 0.f;
        #pragma unroll 8
        for (int j = lane; j < Dn; j += 32) s += p[j];
        #pragma unroll
        for (int o = 16; o; o >>= 1) s += __shfl_down_sync(0xffffffffu, s, o);
        if (!lane) g_wcsum[warp] = s;
    } else {
        size_t i = (size_t)(bx - NBLK_E - NBLK_W - NBLK_S) * 256 + tid;
        float4 x = ((const float4*)w1)[i];
        __half h0 = __float2half_rn(x.x), h1 = __float2half_rn(x.y);
        __half h2 = __float2half_rn(x.z), h3 = __float2half_rn(x.w);
        ((__half2*)g_w1h)[2*i    ] = __halves2half2(h0, h1);
        ((__half2*)g_w1h)[2*i + 1] = __halves2half2(h2, h3);
    }
}

// -------- K2: HMMA fused  P = E @ Wt^T (fp16);  u = sum_e tanh(cp+P)*v ----
__global__ void __launch_bounds__(NTHREADS, 2)
k_attn_mma(const float* __restrict__ c_out, const float* __restrict__ v)
{
    extern __shared__ char smem[];
    const uint32_t sb = smem_u32(smem);
    const int tid   = threadIdx.x;
    const int wid   = tid >> 5;
    const int lane  = tid & 31;
    const int warpM = wid >> 1;
    const int warpN = wid & 1;

    const int et      = blockIdx.x;
    const int rowBase = blockIdx.y * TCM;
    const int h       = blockIdx.z;
    const int eBase   = et * TCN;

    const __half* Ap = g_Ef + (size_t)rowBase * Dn;
    const __half* Bp = g_Wt + ((size_t)h * Dn + eBase) * Dn;

    float* s_cce0 = (float*)(smem + SM_EXTRA);
    float* s_cce1 = s_cce0 + TCN;
    float* s_vv   = s_cce1 + TCN;
    float* s_red  = s_vv + TCN;

    const int b0 = rowBase >> 6;
    {
        int e0 = eBase + (tid & 127);
        float wc0 = g_wcsum[h * Dn + e0];
        if (tid < 128) {
            s_cce0[tid] = c_out[b0 * Dn + e0] * wc0;
            s_vv[tid]   = v[h * Dn + e0];
        } else {
            s_cce1[tid - 128] = c_out[(b0 + 1) * Dn + e0] * wc0;
        }
    }

    int arow[4], ac16[4]; uint32_t aso[4];
    #pragma unroll
    for (int i = 0; i < 4; ++i) {
        int seg = tid + i * NTHREADS;
        arow[i] = seg >> 3; ac16[i] = seg & 7;
        aso[i] = SWZ128((uint32_t)(arow[i] * 128 + ac16[i] * 16));
    }

    float acc[2][8][4];
    #pragma unroll
    for (int mt = 0; mt < 2; ++mt)
        #pragma unroll
        for (int nt = 0; nt < 8; ++nt)
            #pragma unroll
            for (int j = 0; j < 4; ++j) acc[mt][nt][j] = 0.f;

    const uint32_t aRowB = (uint32_t)((warpM * 32 + (lane & 15)) * 128);
    const uint32_t bRowB = (uint32_t)((warpN * 64 + (lane & 15)) * 128);
    const uint32_t colSel = (uint32_t)((lane >> 4) * 16);

    #pragma unroll
    for (int pc = 0; pc < 2; ++pc) {
        const uint32_t st = sb + pc * STAGE_BYTES;
        const int dB = pc * KC;
        #pragma unroll
        for (int i = 0; i < 4; ++i) {
            cp16(st + OFF_A + aso[i], Ap + (size_t)arow[i] * Dn + dB + ac16[i] * 8);
            cp16(st + OFF_B + aso[i], Bp + (size_t)arow[i] * Dn + dB + ac16[i] * 8);
        }
        CP_COMMIT();
    }

    int stage = 0;
    for (int c = 0; c < NCHUNK; ++c) {
        if (c + 2 < NCHUNK) { CP_WAIT(1); } else { CP_WAIT(0); }
        __syncthreads();

        if (c + 2 < NCHUNK) {
            int ns = stage + 2; if (ns >= NSTAGE) ns -= NSTAGE;
            const uint32_t stn = sb + ns * STAGE_BYTES;
            const int dB = (c + 2) * KC;
            #pragma unroll
            for (int i = 0; i < 4; ++i) {
                cp16(stn + OFF_A + aso[i], Ap + (size_t)arow[i] * Dn + dB + ac16[i] * 8);
                cp16(stn + OFF_B + aso[i], Bp + (size_t)arow[i] * Dn + dB + ac16[i] * 8);
            }
            CP_COMMIT();
        }

        const uint32_t st = sb + stage * STAGE_BYTES;
        #pragma unroll
        for (int ks = 0; ks < KC / 16; ++ks) {
            const uint32_t kcol = ks * 32 + colSel;
            uint32_t af[2][4];
            #pragma unroll
            for (int mt = 0; mt < 2; ++mt) {
                uint32_t off = SWZ128(aRowB + (uint32_t)(mt * 16 * 128) + kcol);
                LDSM_X4(af[mt][0], af[mt][1], af[mt][2], af[mt][3], st + OFF_A + off);
            }
            uint32_t bf[8][2];
            #pragma unroll
            for (int p = 0; p < 4; ++p) {
                uint32_t off = SWZ128(bRowB + (uint32_t)(p * 16 * 128) + kcol);
                uint32_t r0, r1, r2, r3;
                LDSM_X4(r0, r1, r2, r3, st + OFF_B + off);
                bf[2*p][0] = r0; bf[2*p][1] = r2;
                bf[2*p+1][0] = r1; bf[2*p+1][1] = r3;
            }
            #pragma unroll
            for (int mt = 0; mt < 2; ++mt)
                #pragma unroll
                for (int nt = 0; nt < 8; ++nt)
                    MMA_F16(acc[mt][nt], af[mt], bf[nt]);
        }
        if (++stage == NSTAGE) stage = 0;
    }

    const int gRow = lane >> 2;
    const int c2   = (lane & 3) * 2;
    const float* cce = (warpM >= 2) ? s_cce1 : s_cce0;

    #pragma unroll
    for (int mt = 0; mt < 2; ++mt) {
        #pragma unroll
        for (int h2 = 0; h2 < 2; ++h2) {
            float p = 0.f;
            #pragma unroll
            for (int nt = 0; nt < 8; ++nt) {
                int e0 = warpN * 64 + nt * 8 + c2;
                float v0 = acc[mt][nt][h2 * 2 + 0];
                float v1 = acc[mt][nt][h2 * 2 + 1];
                p += tanhfast(v0 + cce[e0    ]) * s_vv[e0    ];
                p += tanhfast(v1 + cce[e0 + 1]) * s_vv[e0 + 1];
            }
            p += __shfl_xor_sync(0xffffffffu, p, 1);
            p += __shfl_xor_sync(0xffffffffu, p, 2);
            if ((lane & 3) == 0) {
                int lrow2 = warpM * 32 + mt * 16 + h2 * 8 + gRow;
                s_red[lrow2 * 2 + warpN] = p;
            }
        }
    }
    __syncthreads();

    if (tid < 128) {
        float s = s_red[tid*2] + s_red[tid*2+1];
        int rg = rowBase + tid;
        int bb = rg >> 6, kk = rg & 63;
        g_upart[et * (Bn * Hn * Kn) + ((bb * Hn + h) << 6) + kk] = s;
    }
}

// -------- K4: FUSED softmax + e_att_heads + gate + head_wts + feat ----
// grid: Bn blocks x 512 threads; each thread owns a consecutive d-pair (half2).
__global__ void __launch_bounds__(512)
k_fuse(const int* __restrict__ mask, const float* __restrict__ c_out,
       const float* __restrict__ gate_w, const float* __restrict__ gate_b,
       float* __restrict__ out)
{
    const int b = blockIdx.x, tid = threadIdx.x;
    const int lane = tid & 31, wid = tid >> 5;   // 16 warps

    __shared__ float red[256];
    __shared__ float sal[256];          // alpha [h][k]
    __shared__ float gred[16][5];
    __shared__ float shw[4];

    // ---- softmax over k within each h (4 groups of 64 threads) ----
    float s = 0.f;
    if (tid < 256) {
        const int hh = tid >> 6, kk = tid & 63;
        #pragma unroll
        for (int nt = 0; nt < NET; ++nt)
            s += g_upart[nt * (Bn*Hn*Kn) + ((b * Hn + hh) << 6) + kk];
        if (mask[b * Kn + kk] == 0) s = __int_as_float(0xff800000);
        red[tid] = s;
    }
    __syncthreads();
    #pragma unroll
    for (int o = 32; o; o >>= 1) {
        if (tid < 256 && (tid & 63) < o) red[tid] = fmaxf(red[tid], red[tid + o]);
        __syncthreads();
    }
    float ex = 0.f;
    if (tid < 256) ex = __expf(s - red[(tid >> 6) << 6]);
    __syncthreads();
    if (tid < 256) red[tid] = ex;
    __syncthreads();
    #pragma unroll
    for (int o = 32; o; o >>= 1) {
        if (tid < 256 && (tid & 63) < o) red[tid] += red[tid + o];
        __syncthreads();
    }
    if (tid < 256) {
        float al = ex / red[(tid >> 6) << 6];
        sal[tid] = al;
        out[ALPHA_OFF + b * (Hn*Kn) + tid] = al;
    }
    __syncthreads();

    // ---- e_att_heads for d-pair (half2 loads, 128B warp transactions) ----
    const __half2* ep2 = (const __half2*)(g_Ef + (size_t)b * Kn * Dn) + tid;
    float2 A0 = {0.f, 0.f}, A1 = {0.f, 0.f}, A2 = {0.f, 0.f}, A3 = {0.f, 0.f};
    #pragma unroll 8
    for (int k = 0; k < Kn; ++k) {
        float2 ev = __half22float2(ep2[k * (Dn/2)]);
        float s0 = sal[k], s1 = sal[64+k], s2 = sal[128+k], s3 = sal[192+k];
        A0.x = fmaf(s0, ev.x, A0.x); A0.y = fmaf(s0, ev.y, A0.y);
        A1.x = fmaf(s1, ev.x, A1.x); A1.y = fmaf(s1, ev.y, A1.y);
        A2.x = fmaf(s2, ev.x, A2.x); A2.y = fmaf(s2, ev.y, A2.y);
        A3.x = fmaf(s3, ev.x, A3.x); A3.y = fmaf(s3, ev.y, A3.y);
    }

    // ---- gate: per-thread pair partials; warp + cross-warp reduce ----
    float2 cv  = ((const float2*)(c_out + (size_t)b * Dn))[tid];
    float2 gwc = ((const float2*)gate_w)[tid];
    float2 gwe = ((const float2*)(gate_w + Dn))[tid];
    float pv[5];
    pv[0] = cv.x * gwc.x + cv.y * gwc.y;
    pv[1] = A0.x * gwe.x + A0.y * gwe.y;
    pv[2] = A1.x * gwe.x + A1.y * gwe.y;
    pv[3] = A2.x * gwe.x + A2.y * gwe.y;
    pv[4] = A3.x * gwe.x + A3.y * gwe.y;
    #pragma unroll
    for (int i = 0; i < 5; ++i) {
        float x = pv[i];
        #pragma unroll
        for (int o = 16; o; o >>= 1) x += __shfl_xor_sync(0xffffffffu, x, o);
        if (!lane) gred[wid][i] = x;
    }
    __syncthreads();
    if (wid == 0) {
        #pragma unroll
        for (int i = 0; i < 5; ++i) {
            float x = (lane < 16) ? gred[lane][i] : 0.f;
            #pragma unroll
            for (int o = 8; o; o >>= 1) x += __shfl_xor_sync(0xffffffffu, x, o);
            if (!lane) gred[0][i] = x;
        }
        if (!lane) {
            float gb = gate_b[0];
            float g0 = gred[0][0] + gred[0][1] + gb, g1 = gred[0][0] + gred[0][2] + gb;
            float g2 = gred[0][0] + gred[0][3] + gb, g3 = gred[0][0] + gred[0][4] + gb;
            float mx = fmaxf(fmaxf(g0, g1), fmaxf(g2, g3));
            float e0 = __expf(g0 - mx), e1 = __expf(g1 - mx);
            float e2 = __expf(g2 - mx), e3 = __expf(g3 - mx);
            float inv = 1.f / (e0 + e1 + e2 + e3);
            shw[0] = e0*inv; shw[1] = e1*inv; shw[2] = e2*inv; shw[3] = e3*inv;
            out[HW_OFF + b*Hn + 0] = shw[0]; out[HW_OFF + b*Hn + 1] = shw[1];
            out[HW_OFF + b*Hn + 2] = shw[2]; out[HW_OFF + b*Hn + 3] = shw[3];
        }
    }
    __syncthreads();

    // ---- feature vector (fp16, half2 stores) ----
    float hw0 = shw[0], hw1 = shw[1], hw2 = shw[2], hw3 = shw[3];
    float2 ea;
    ea.x = hw0*A0.x + hw1*A1.x + hw2*A2.x + hw3*A3.x;
    ea.y = hw0*A0.y + hw1*A1.y + hw2*A2.y + hw3*A3.y;
    __half2* fb = (__half2*)(g_feath + (size_t)b * KD);
    fb[            tid] = __floats2half2_rn(cv.x, cv.y);
    fb[ (Dn/2)   + tid] = __floats2half2_rn(ea.x, ea.y);
    fb[2*(Dn/2)  + tid] = __floats2half2_rn(fabsf(cv.x - ea.x), fabsf(cv.y - ea.y));
    fb[3*(Dn/2)  + tid] = __floats2half2_rn(cv.x * ea.x, cv.y * ea.y);
}

// -------- K7: hid_part = feat @ w1.T via HMMA fp16 --------
// CTA 128(M) x 64(N), 8 warps (warp tile 32x32), split-k=8 -> 256 CTAs
__global__ void __launch_bounds__(NTHREADS, 2)
k_mlp1() {
    extern __shared__ char smem[];
    const uint32_t sb = smem_u32(smem);
    const int tid   = threadIdx.x;
    const int wid   = tid >> 5;
    const int lane  = tid & 31;
    const int warpM = wid >> 1;     // 0..3 (32 rows)
    const int warpN = wid & 1;      // 0..1 (32 cols)

    const int oBase   = blockIdx.x * TCN_M;
    const int rowBase = blockIdx.y * TCM;
    const int z       = blockIdx.z;
    const int kBase   = z * KSPAN;

    const __half* Ap = g_feath + (size_t)rowBase * KD + kBase;
    const __half* Bp = g_w1h   + (size_t)oBase * KD + kBase;

    // A: 1024 16B segs -> 4/thread; B: 512 segs -> 2/thread
    int arow[4], ac16[4]; uint32_t aso[4];
    #pragma unroll
    for (int i = 0; i < 4; ++i) {
        int seg = tid + i * NTHREADS;
        arow[i] = seg >> 3; ac16[i] = seg & 7;
        aso[i] = SWZ128((uint32_t)(arow[i] * 128 + ac16[i] * 16));
    }

    float acc[2][4][4];
    #pragma unroll
    for (int mt = 0; mt < 2; ++mt)
        #pragma unroll
        for (int nt = 0; nt < 4; ++nt)
            #pragma unroll
            for (int j = 0; j < 4; ++j) acc[mt][nt][j] = 0.f;

    const uint32_t aRowB = (uint32_t)((warpM * 32 + (lane & 15)) * 128);
    const uint32_t bRowB = (uint32_t)((warpN * 32 + (lane & 15)) * 128);
    const uint32_t colSel = (uint32_t)((lane >> 4) * 16);

    #pragma unroll
    for (int pc = 0; pc < 2; ++pc) {
        const uint32_t st = sb + pc * STAGE_M;
        const int dB = pc * KC;
        #pragma unroll
        for (int i = 0; i < 4; ++i)
            cp16(st + OFF_A + aso[i], Ap + (size_t)arow[i] * KD + dB + ac16[i] * 8);
        #pragma unroll
        for (int i = 0; i < 2; ++i)
            cp16(st + OFF_B_M + aso[i], Bp + (size_t)arow[i] * KD + dB + ac16[i] * 8);
        CP_COMMIT();
    }

    int stage = 0;
    for (int c = 0; c < NCHUNK_M; ++c) {
        if (c + 2 < NCHUNK_M) { CP_WAIT(1); } else { CP_WAIT(0); }
        __syncthreads();

        if (c + 2 < NCHUNK_M) {
            int ns = stage + 2; if (ns >= NSTAGE) ns -= NSTAGE;
            const uint32_t stn = sb + ns * STAGE_M;
            const int dB = (c + 2) * KC;
            #pragma unroll
            for (int i = 0; i < 4; ++i)
                cp16(stn + OFF_A + aso[i], Ap + (size_t)arow[i] * KD + dB + ac16[i] * 8);
            #pragma unroll
            for (int i = 0; i < 2; ++i)
                cp16(stn + OFF_B_M + aso[i], Bp + (size_t)arow[i] * KD + dB + ac16[i] * 8);
            CP_COMMIT();
        }

        const uint32_t st = sb + stage * STAGE_M;
        #pragma unroll
        for (int ks = 0; ks < KC / 16; ++ks) {
            const uint32_t kcol = ks * 32 + colSel;
            uint32_t af[2][4];
            #pragma unroll
            for (int mt = 0; mt < 2; ++mt) {
                uint32_t off = SWZ128(aRowB + (uint32_t)(mt * 16 * 128) + kcol);
                LDSM_X4(af[mt][0], af[mt][1], af[mt][2], af[mt][3], st + OFF_A + off);
            }
            uint32_t bf[4][2];
            #pragma unroll
            for (int p = 0; p < 2; ++p) {
                uint32_t off = SWZ128(bRowB + (uint32_t)(p * 16 * 128) + kcol);
                uint32_t r0, r1, r2, r3;
                LDSM_X4(r0, r1, r2, r3, st + OFF_B_M + off);
                bf[2*p][0] = r0; bf[2*p][1] = r2;
                bf[2*p+1][0] = r1; bf[2*p+1][1] = r3;
            }
            #pragma unroll
            for (int mt = 0; mt < 2; ++mt)
                #pragma unroll
                for (int nt = 0; nt < 4; ++nt)
                    MMA_F16(acc[mt][nt], af[mt], bf[nt]);
        }
        if (++stage == NSTAGE) stage = 0;
    }

    float* slab = g_hidpart + (size_t)z * (Bn * Dn);
    const int gRow = lane >> 2;
    const int gCol = (lane & 3) * 2;
    #pragma unroll
    for (int mt = 0; mt < 2; ++mt)
        #pragma unroll
        for (int h2 = 0; h2 < 2; ++h2) {
            int row = rowBase + warpM * 32 + mt * 16 + h2 * 8 + gRow;
            #pragma unroll
            for (int nt = 0; nt < 4; ++nt) {
                int col = oBase + warpN * 32 + nt * 8 + gCol;
                float2 val = make_float2(acc[mt][nt][h2*2], acc[mt][nt][h2*2+1]);
                *(float2*)&slab[(size_t)row * Dn + col] = val;
            }
        }
}

// -------- K8: relu(sum hid_parts + b1) @ w2.T + b2 -> logits --------
__global__ void k_logits(const float* __restrict__ b1, const float* __restrict__ w2,
                         const float* __restrict__ b2, float* __restrict__ out) {
    const int b = blockIdx.x, tid = threadIdx.x;
    float a0 = 0.f, a1 = 0.f, a2 = 0.f;
    for (int d = tid; d < Dn; d += 128) {
        float hp = b1[d];
        #pragma unroll
        for (int zz = 0; zz < SPLITK; ++zz)
            hp += g_hidpart[(size_t)zz * (Bn*Dn) + b*Dn + d];
        hp = fmaxf(hp, 0.f);
        a0 = fmaf(hp, w2[        d], a0);
        a1 = fmaf(hp, w2[  Dn + d], a1);
        a2 = fmaf(hp, w2[2*Dn + d], a2);
    }
    __shared__ float red[128];
    __shared__ float vals[3];
    float pv[3] = {a0, a1, a2};
    for (int i = 0; i < 3; ++i) {
        red[tid] = pv[i]; __syncthreads();
        #pragma unroll
        for (int o = 64; o; o >>= 1) { if (tid < o) red[tid] += red[tid+o]; __syncthreads(); }
        if (!tid) vals[i] = red[0];
        __syncthreads();
    }
    if (!tid) {
        out[b*NLn + 0] = vals[0] + b2[0];
        out[b*NLn + 1] = vals[1] + b2[1];
        out[b*NLn + 2] = vals[2] + b2[2];
    }
}

extern "C" void kernel_launch(void* const* d_in, const int* in_sizes, int n_in,
                              void* d_out, int out_size) {
    const float* c_out  = (const float*)d_in[0];
    const float* e_emb  = (const float*)d_in[1];
    const int*   emask  = (const int*)  d_in[2];
    const float* W_c    = (const float*)d_in[3];
    const float* W_e    = (const float*)d_in[4];
    const float* v      = (const float*)d_in[5];
    const float* gate_w = (const float*)d_in[6];
    const float* gate_b = (const float*)d_in[7];
    const float* w1     = (const float*)d_in[8];
    const float* b1     = (const float*)d_in[9];
    const float* w2     = (const float*)d_in[10];
    const float* b2     = (const float*)d_in[11];
    float* out = (float*)d_out;

    cudaFuncSetAttribute(k_attn_mma, cudaFuncAttributeMaxDynamicSharedMemorySize, SMEM_TOTAL);
    cudaFuncSetAttribute(k_mlp1, cudaFuncAttributeMaxDynamicSharedMemorySize, SMEM_TOTAL_M);

    k_prep<<<NBLK_E + NBLK_W + NBLK_S + NBLK_W1, 256>>>(e_emb, W_e, W_c, w1);
    k_attn_mma<<<dim3(NET, (Bn*Kn)/TCM, Hn), NTHREADS, SMEM_TOTAL>>>(c_out, v);
    k_fuse<<<Bn, 512>>>(emask, c_out, gate_w, gate_b, out);
    k_mlp1<<<dim3(Dn/TCN_M, Bn/TCM, SPLITK), NTHREADS, SMEM_TOTAL_M>>>();
    k_logits<<<Bn, 128>>>(b1, w2, b2, out);
}

// round 15
// speedup vs baseline: 1.0187x; 1.0014x over previous
#include <cuda_runtime.h>
#include <cuda_fp16.h>
#include <math.h>
#include <stdint.h>

// Problem shapes
#define Bn  256
#define Kn  64
#define Dn  1024
#define KD  4096                // MLP1 K dim = 4*Dn
#define Hn  4
#define NLn 3

// Output layout in d_out (fp32): logits (B*NL), alpha (B*H*K), head_weights (B*H)
#define ALPHA_OFF 768
#define HW_OFF    (768 + Bn*Hn*Kn)

// HMMA GEMM tiling: CTA 128x128, warp tile 32x64, 8 warps, 2 CTAs/SM
#define TCM 128
#define TCN 128
#define KC  64                  // K elems per chunk (64 fp16 = 128B row)
#define NCHUNK (Dn / KC)        // 16
#define NET    (Dn / TCN)       // 8 e-tiles
#define NTHREADS 256
#define NSTAGE 3

// MLP1: CTA 128x64, split-k=8 -> 256 CTAs, 8-chunk pipeline
#define SPLITK 8
#define KSPAN  (KD / SPLITK)    // 512
#define NCHUNK_M (KSPAN / KC)   // 8
#define TCN_M 64
#define GRID_M 256              // total mlp1 CTAs (16 x 2 x 8)

typedef unsigned long long u64;

// -------- scratch (static device globals; no allocation allowed) --------
__device__ float g_wcsum[Hn * Dn];
__device__ float g_upart[NET * Bn * Hn * Kn];       // 2 MB
__device__ float g_hidpart[SPLITK * Bn * Dn];       // 8 MB
__device__ int   g_done;                            // mlp1 completion counter
// fp16 operands (single-rounded)
__device__ __half g_Ef[Bn * Kn * Dn];    // 32 MB
__device__ __half g_Wt[Hn * Dn * Dn];    // 8 MB  (transposed: [h][e][d])
__device__ __half g_w1h[Dn * KD];        // 8 MB  (w1 fp16, [N=1024][K=4096])
__device__ __half g_feath[Bn * KD];      // 2 MB  (features fp16, [256][4096])

// -------- helpers --------
__device__ __forceinline__ uint32_t smem_u32(const void* p) {
    uint32_t a;
    asm("{ .reg .u64 t; cvta.to.shared.u64 t, %1; cvt.u32.u64 %0, t; }" : "=r"(a) : "l"(p));
    return a;
}
__device__ __forceinline__ float tanhfast(float x) {
    float y; asm("tanh.approx.f32 %0, %1;" : "=f"(y) : "f"(x)); return y;
}
#define SWZ128(o) ((o) ^ (((o) >> 3) & 0x70))

__device__ __forceinline__ void cp16(uint32_t saddr, const void* gptr) {
    asm volatile("cp.async.cg.shared.global [%0], [%1], 16;"
                 :: "r"(saddr), "l"(__cvta_generic_to_global(gptr)) : "memory");
}
#define CP_COMMIT() asm volatile("cp.async.commit_group;" ::: "memory")
#define CP_WAIT(n)  asm volatile("cp.async.wait_group %0;" :: "n"(n) : "memory")

#define LDSM_X4(r0, r1, r2, r3, addr) \
    asm volatile("ldmatrix.sync.aligned.m8n8.x4.shared.b16 {%0,%1,%2,%3}, [%4];" \
                 : "=r"(r0), "=r"(r1), "=r"(r2), "=r"(r3) : "r"(addr))

#define MMA_F16(c, a, b) \
    asm volatile("mma.sync.aligned.m16n8k16.row.col.f32.f16.f16.f32 " \
                 "{%0,%1,%2,%3}, {%4,%5,%6,%7}, {%8,%9}, {%0,%1,%2,%3};" \
                 : "+f"((c)[0]), "+f"((c)[1]), "+f"((c)[2]), "+f"((c)[3]) \
                 : "r"((a)[0]), "r"((a)[1]), "r"((a)[2]), "r"((a)[3]), \
                   "r"((b)[0]), "r"((b)[1]))

// attn smem stage layout: A(16KB) + B(16KB) = 32KB per stage
#define OFF_A   0
#define OFF_B   16384
#define STAGE_BYTES 32768
#define SM_EXTRA (NSTAGE * STAGE_BYTES)
#define SMEM_TOTAL (NSTAGE * STAGE_BYTES + 4096)      // 102400 -> 2 CTAs/SM

// mlp1 smem stage layout: A(16KB) + B(8KB) = 24KB per stage
#define OFF_B_M  16384
#define STAGE_M  24576
#define SMEM_TOTAL_M (NSTAGE * STAGE_M)               // 73728 -> 2 CTAs/SM

// -------- K0: preprocessing (cvtE | cvtW | wcsum); also resets g_done ----
#define NBLK_E  (Bn*Kn*Dn/4/256)      // 16384
#define NBLK_W  ((Dn/32)*(Dn/32)*Hn)  // 4096
#define NBLK_S  (Hn*Dn*32/256)        // 512
__global__ void k_prep(const float* __restrict__ e, const float* __restrict__ W,
                       const float* __restrict__ W_c) {
    __shared__ float t[32][33];
    const int bx = blockIdx.x;
    const int tid = threadIdx.x;
    if (bx == 0 && tid == 0) g_done = 0;
    if (bx < NBLK_E) {
        size_t i = (size_t)bx * 256 + tid;   // over float4s
        float4 x = ((const float4*)e)[i];
        __half h0 = __float2half_rn(x.x), h1 = __float2half_rn(x.y);
        __half h2 = __float2half_rn(x.z), h3 = __float2half_rn(x.w);
        ((__half2*)g_Ef)[2*i    ] = __halves2half2(h0, h1);
        ((__half2*)g_Ef)[2*i + 1] = __halves2half2(h2, h3);
    } else if (bx < NBLK_E + NBLK_W) {
        const int b  = bx - NBLK_E;
        const int h  = b >> 10;
        const int dB = ((b & 1023) >> 5) * 32;
        const int eB = (b & 31) * 32;
        const int lx = tid & 31, ly = tid >> 5;  // 32 x 8
        #pragma unroll
        for (int r = 0; r < 4; ++r)
            t[ly + 8*r][lx] = W[((size_t)h*Dn + dB + ly + 8*r) * Dn + eB + lx];
        __syncthreads();
        #pragma unroll
        for (int r = 0; r < 4; ++r) {
            float x = t[lx][ly + 8*r];
            size_t oi = ((size_t)h*Dn + eB + ly + 8*r) * Dn + dB + lx;
            g_Wt[oi] = __float2half_rn(x);
        }
    } else {
        int warp = (((bx - NBLK_E - NBLK_W) << 8) + tid) >> 5;
        int lane = tid & 31;
        const float* p = W_c + (size_t)warp * Dn;
        float s = 0.f;
        #pragma unroll 8
        for (int j = lane; j < Dn; j += 32) s += p[j];
        #pragma unroll
        for (int o = 16; o; o >>= 1) s += __shfl_down_sync(0xffffffffu, s, o);
        if (!lane) g_wcsum[warp] = s;
    }
}

// -------- K2: HMMA fused  P = E @ Wt^T (fp16);  u = sum_e tanh(cp+P)*v ----
__global__ void __launch_bounds__(NTHREADS, 2)
k_attn_mma(const float* __restrict__ c_out, const float* __restrict__ v)
{
    extern __shared__ char smem[];
    const uint32_t sb = smem_u32(smem);
    const int tid   = threadIdx.x;
    const int wid   = tid >> 5;
    const int lane  = tid & 31;
    const int warpM = wid >> 1;
    const int warpN = wid & 1;

    const int et      = blockIdx.x;
    const int rowBase = blockIdx.y * TCM;
    const int h       = blockIdx.z;
    const int eBase   = et * TCN;

    const __half* Ap = g_Ef + (size_t)rowBase * Dn;
    const __half* Bp = g_Wt + ((size_t)h * Dn + eBase) * Dn;

    float* s_cce0 = (float*)(smem + SM_EXTRA);
    float* s_cce1 = s_cce0 + TCN;
    float* s_vv   = s_cce1 + TCN;
    float* s_red  = s_vv + TCN;

    const int b0 = rowBase >> 6;
    {
        int e0 = eBase + (tid & 127);
        float wc0 = g_wcsum[h * Dn + e0];
        if (tid < 128) {
            s_cce0[tid] = c_out[b0 * Dn + e0] * wc0;
            s_vv[tid]   = v[h * Dn + e0];
        } else {
            s_cce1[tid - 128] = c_out[(b0 + 1) * Dn + e0] * wc0;
        }
    }

    int arow[4], ac16[4]; uint32_t aso[4];
    #pragma unroll
    for (int i = 0; i < 4; ++i) {
        int seg = tid + i * NTHREADS;
        arow[i] = seg >> 3; ac16[i] = seg & 7;
        aso[i] = SWZ128((uint32_t)(arow[i] * 128 + ac16[i] * 16));
    }

    float acc[2][8][4];
    #pragma unroll
    for (int mt = 0; mt < 2; ++mt)
        #pragma unroll
        for (int nt = 0; nt < 8; ++nt)
            #pragma unroll
            for (int j = 0; j < 4; ++j) acc[mt][nt][j] = 0.f;

    const uint32_t aRowB = (uint32_t)((warpM * 32 + (lane & 15)) * 128);
    const uint32_t bRowB = (uint32_t)((warpN * 64 + (lane & 15)) * 128);
    const uint32_t colSel = (uint32_t)((lane >> 4) * 16);

    #pragma unroll
    for (int pc = 0; pc < 2; ++pc) {
        const uint32_t st = sb + pc * STAGE_BYTES;
        const int dB = pc * KC;
        #pragma unroll
        for (int i = 0; i < 4; ++i) {
            cp16(st + OFF_A + aso[i], Ap + (size_t)arow[i] * Dn + dB + ac16[i] * 8);
            cp16(st + OFF_B + aso[i], Bp + (size_t)arow[i] * Dn + dB + ac16[i] * 8);
        }
        CP_COMMIT();
    }

    int stage = 0;
    for (int c = 0; c < NCHUNK; ++c) {
        if (c + 2 < NCHUNK) { CP_WAIT(1); } else { CP_WAIT(0); }
        __syncthreads();

        if (c + 2 < NCHUNK) {
            int ns = stage + 2; if (ns >= NSTAGE) ns -= NSTAGE;
            const uint32_t stn = sb + ns * STAGE_BYTES;
            const int dB = (c + 2) * KC;
            #pragma unroll
            for (int i = 0; i < 4; ++i) {
                cp16(stn + OFF_A + aso[i], Ap + (size_t)arow[i] * Dn + dB + ac16[i] * 8);
                cp16(stn + OFF_B + aso[i], Bp + (size_t)arow[i] * Dn + dB + ac16[i] * 8);
            }
            CP_COMMIT();
        }

        const uint32_t st = sb + stage * STAGE_BYTES;
        #pragma unroll
        for (int ks = 0; ks < KC / 16; ++ks) {
            const uint32_t kcol = ks * 32 + colSel;
            uint32_t af[2][4];
            #pragma unroll
            for (int mt = 0; mt < 2; ++mt) {
                uint32_t off = SWZ128(aRowB + (uint32_t)(mt * 16 * 128) + kcol);
                LDSM_X4(af[mt][0], af[mt][1], af[mt][2], af[mt][3], st + OFF_A + off);
            }
            uint32_t bf[8][2];
            #pragma unroll
            for (int p = 0; p < 4; ++p) {
                uint32_t off = SWZ128(bRowB + (uint32_t)(p * 16 * 128) + kcol);
                uint32_t r0, r1, r2, r3;
                LDSM_X4(r0, r1, r2, r3, st + OFF_B + off);
                bf[2*p][0] = r0; bf[2*p][1] = r2;
                bf[2*p+1][0] = r1; bf[2*p+1][1] = r3;
            }
            #pragma unroll
            for (int mt = 0; mt < 2; ++mt)
                #pragma unroll
                for (int nt = 0; nt < 8; ++nt)
                    MMA_F16(acc[mt][nt], af[mt], bf[nt]);
        }
        if (++stage == NSTAGE) stage = 0;
    }

    const int gRow = lane >> 2;
    const int c2   = (lane & 3) * 2;
    const float* cce = (warpM >= 2) ? s_cce1 : s_cce0;

    #pragma unroll
    for (int mt = 0; mt < 2; ++mt) {
        #pragma unroll
        for (int h2 = 0; h2 < 2; ++h2) {
            float p = 0.f;
            #pragma unroll
            for (int nt = 0; nt < 8; ++nt) {
                int e0 = warpN * 64 + nt * 8 + c2;
                float v0 = acc[mt][nt][h2 * 2 + 0];
                float v1 = acc[mt][nt][h2 * 2 + 1];
                p += tanhfast(v0 + cce[e0    ]) * s_vv[e0    ];
                p += tanhfast(v1 + cce[e0 + 1]) * s_vv[e0 + 1];
            }
            p += __shfl_xor_sync(0xffffffffu, p, 1);
            p += __shfl_xor_sync(0xffffffffu, p, 2);
            if ((lane & 3) == 0) {
                int lrow2 = warpM * 32 + mt * 16 + h2 * 8 + gRow;
                s_red[lrow2 * 2 + warpN] = p;
            }
        }
    }
    __syncthreads();

    if (tid < 128) {
        float s = s_red[tid*2] + s_red[tid*2+1];
        int rg = rowBase + tid;
        int bb = rg >> 6, kk = rg & 63;
        g_upart[et * (Bn * Hn * Kn) + ((bb * Hn + h) << 6) + kk] = s;
    }
}

// -------- K4: FUSED softmax + e_att_heads + gate + head_wts + feat
//          PLUS w1 -> fp16 conversion on the extra blocks (bx >= Bn) ----
#define NBLK_W1F (Dn*KD/4/512)   // 2048 blocks of 512 threads over float4s
__global__ void __launch_bounds__(512)
k_fuse(const int* __restrict__ mask, const float* __restrict__ c_out,
       const float* __restrict__ gate_w, const float* __restrict__ gate_b,
       const float* __restrict__ w1, float* __restrict__ out)
{
    const int tid = threadIdx.x;
    if (blockIdx.x >= Bn) {
        // w1 -> fp16 copy (no barriers on this path); consumed by k_mlp1 later
        size_t i = (size_t)(blockIdx.x - Bn) * 512 + tid;
        float4 x = ((const float4*)w1)[i];
        __half h0 = __float2half_rn(x.x), h1 = __float2half_rn(x.y);
        __half h2 = __float2half_rn(x.z), h3 = __float2half_rn(x.w);
        ((__half2*)g_w1h)[2*i    ] = __halves2half2(h0, h1);
        ((__half2*)g_w1h)[2*i + 1] = __halves2half2(h2, h3);
        return;
    }
    const int b = blockIdx.x;
    const int lane = tid & 31, wid = tid >> 5;   // 16 warps

    __shared__ float red[256];
    __shared__ float sal[256];          // alpha [h][k]
    __shared__ float gred[16][5];
    __shared__ float shw[4];

    // ---- softmax over k within each h (4 groups of 64 threads) ----
    float s = 0.f;
    if (tid < 256) {
        const int hh = tid >> 6, kk = tid & 63;
        #pragma unroll
        for (int nt = 0; nt < NET; ++nt)
            s += g_upart[nt * (Bn*Hn*Kn) + ((b * Hn + hh) << 6) + kk];
        if (mask[b * Kn + kk] == 0) s = __int_as_float(0xff800000);
        red[tid] = s;
    }
    __syncthreads();
    #pragma unroll
    for (int o = 32; o; o >>= 1) {
        if (tid < 256 && (tid & 63) < o) red[tid] = fmaxf(red[tid], red[tid + o]);
        __syncthreads();
    }
    float ex = 0.f;
    if (tid < 256) ex = __expf(s - red[(tid >> 6) << 6]);
    __syncthreads();
    if (tid < 256) red[tid] = ex;
    __syncthreads();
    #pragma unroll
    for (int o = 32; o; o >>= 1) {
        if (tid < 256 && (tid & 63) < o) red[tid] += red[tid + o];
        __syncthreads();
    }
    if (tid < 256) {
        float al = ex / red[(tid >> 6) << 6];
        sal[tid] = al;
        out[ALPHA_OFF + b * (Hn*Kn) + tid] = al;
    }
    __syncthreads();

    // ---- e_att_heads for d-pair (half2 loads) ----
    const __half2* ep2 = (const __half2*)(g_Ef + (size_t)b * Kn * Dn) + tid;
    float2 A0 = {0.f, 0.f}, A1 = {0.f, 0.f}, A2 = {0.f, 0.f}, A3 = {0.f, 0.f};
    #pragma unroll 8
    for (int k = 0; k < Kn; ++k) {
        float2 ev = __half22float2(ep2[k * (Dn/2)]);
        float s0 = sal[k], s1 = sal[64+k], s2 = sal[128+k], s3 = sal[192+k];
        A0.x = fmaf(s0, ev.x, A0.x); A0.y = fmaf(s0, ev.y, A0.y);
        A1.x = fmaf(s1, ev.x, A1.x); A1.y = fmaf(s1, ev.y, A1.y);
        A2.x = fmaf(s2, ev.x, A2.x); A2.y = fmaf(s2, ev.y, A2.y);
        A3.x = fmaf(s3, ev.x, A3.x); A3.y = fmaf(s3, ev.y, A3.y);
    }

    // ---- gate: per-thread pair partials; warp + cross-warp reduce ----
    float2 cv  = ((const float2*)(c_out + (size_t)b * Dn))[tid];
    float2 gwc = ((const float2*)gate_w)[tid];
    float2 gwe = ((const float2*)(gate_w + Dn))[tid];
    float pv[5];
    pv[0] = cv.x * gwc.x + cv.y * gwc.y;
    pv[1] = A0.x * gwe.x + A0.y * gwe.y;
    pv[2] = A1.x * gwe.x + A1.y * gwe.y;
    pv[3] = A2.x * gwe.x + A2.y * gwe.y;
    pv[4] = A3.x * gwe.x + A3.y * gwe.y;
    #pragma unroll
    for (int i = 0; i < 5; ++i) {
        float x = pv[i];
        #pragma unroll
        for (int o = 16; o; o >>= 1) x += __shfl_xor_sync(0xffffffffu, x, o);
        if (!lane) gred[wid][i] = x;
    }
    __syncthreads();
    if (wid == 0) {
        #pragma unroll
        for (int i = 0; i < 5; ++i) {
            float x = (lane < 16) ? gred[lane][i] : 0.f;
            #pragma unroll
            for (int o = 8; o; o >>= 1) x += __shfl_xor_sync(0xffffffffu, x, o);
            if (!lane) gred[0][i] = x;
        }
        if (!lane) {
            float gb = gate_b[0];
            float g0 = gred[0][0] + gred[0][1] + gb, g1 = gred[0][0] + gred[0][2] + gb;
            float g2 = gred[0][0] + gred[0][3] + gb, g3 = gred[0][0] + gred[0][4] + gb;
            float mx = fmaxf(fmaxf(g0, g1), fmaxf(g2, g3));
            float e0 = __expf(g0 - mx), e1 = __expf(g1 - mx);
            float e2 = __expf(g2 - mx), e3 = __expf(g3 - mx);
            float inv = 1.f / (e0 + e1 + e2 + e3);
            shw[0] = e0*inv; shw[1] = e1*inv; shw[2] = e2*inv; shw[3] = e3*inv;
            out[HW_OFF + b*Hn + 0] = shw[0]; out[HW_OFF + b*Hn + 1] = shw[1];
            out[HW_OFF + b*Hn + 2] = shw[2]; out[HW_OFF + b*Hn + 3] = shw[3];
        }
    }
    __syncthreads();

    // ---- feature vector (fp16, half2 stores) ----
    float hw0 = shw[0], hw1 = shw[1], hw2 = shw[2], hw3 = shw[3];
    float2 ea;
    ea.x = hw0*A0.x + hw1*A1.x + hw2*A2.x + hw3*A3.x;
    ea.y = hw0*A0.y + hw1*A1.y + hw2*A2.y + hw3*A3.y;
    __half2* fb = (__half2*)(g_feath + (size_t)b * KD);
    fb[            tid] = __floats2half2_rn(cv.x, cv.y);
    fb[ (Dn/2)   + tid] = __floats2half2_rn(ea.x, ea.y);
    fb[2*(Dn/2)  + tid] = __floats2half2_rn(fabsf(cv.x - ea.x), fabsf(cv.y - ea.y));
    fb[3*(Dn/2)  + tid] = __floats2half2_rn(cv.x * ea.x, cv.y * ea.y);
}

// -------- K7: hid_part = feat @ w1.T (HMMA) + fused logits tail --------
// CTA 128(M) x 64(N), 8 warps, split-k=8 -> 256 CTAs (all co-resident).
// After all CTAs finish their slab, each CTA computes logits for one b-row.
__global__ void __launch_bounds__(NTHREADS, 2)
k_mlp1(const float* __restrict__ b1, const float* __restrict__ w2,
       const float* __restrict__ b2, float* __restrict__ out) {
    extern __shared__ char smem[];
    const uint32_t sb = smem_u32(smem);
    const int tid   = threadIdx.x;
    const int wid   = tid >> 5;
    const int lane  = tid & 31;
    const int warpM = wid >> 1;     // 0..3 (32 rows)
    const int warpN = wid & 1;      // 0..1 (32 cols)

    const int oBase   = blockIdx.x * TCN_M;
    const int rowBase = blockIdx.y * TCM;
    const int z       = blockIdx.z;
    const int kBase   = z * KSPAN;

    const __half* Ap = g_feath + (size_t)rowBase * KD + kBase;
    const __half* Bp = g_w1h   + (size_t)oBase * KD + kBase;

    int arow[4], ac16[4]; uint32_t aso[4];
    #pragma unroll
    for (int i = 0; i < 4; ++i) {
        int seg = tid + i * NTHREADS;
        arow[i] = seg >> 3; ac16[i] = seg & 7;
        aso[i] = SWZ128((uint32_t)(arow[i] * 128 + ac16[i] * 16));
    }

    float acc[2][4][4];
    #pragma unroll
    for (int mt = 0; mt < 2; ++mt)
        #pragma unroll
        for (int nt = 0; nt < 4; ++nt)
            #pragma unroll
            for (int j = 0; j < 4; ++j) acc[mt][nt][j] = 0.f;

    const uint32_t aRowB = (uint32_t)((warpM * 32 + (lane & 15)) * 128);
    const uint32_t bRowB = (uint32_t)((warpN * 32 + (lane & 15)) * 128);
    const uint32_t colSel = (uint32_t)((lane >> 4) * 16);

    #pragma unroll
    for (int pc = 0; pc < 2; ++pc) {
        const uint32_t st = sb + pc * STAGE_M;
        const int dB = pc * KC;
        #pragma unroll
        for (int i = 0; i < 4; ++i)
            cp16(st + OFF_A + aso[i], Ap + (size_t)arow[i] * KD + dB + ac16[i] * 8);
        #pragma unroll
        for (int i = 0; i < 2; ++i)
            cp16(st + OFF_B_M + aso[i], Bp + (size_t)arow[i] * KD + dB + ac16[i] * 8);
        CP_COMMIT();
    }

    int stage = 0;
    for (int c = 0; c < NCHUNK_M; ++c) {
        if (c + 2 < NCHUNK_M) { CP_WAIT(1); } else { CP_WAIT(0); }
        __syncthreads();

        if (c + 2 < NCHUNK_M) {
            int ns = stage + 2; if (ns >= NSTAGE) ns -= NSTAGE;
            const uint32_t stn = sb + ns * STAGE_M;
            const int dB = (c + 2) * KC;
            #pragma unroll
            for (int i = 0; i < 4; ++i)
                cp16(stn + OFF_A + aso[i], Ap + (size_t)arow[i] * KD + dB + ac16[i] * 8);
            #pragma unroll
            for (int i = 0; i < 2; ++i)
                cp16(stn + OFF_B_M + aso[i], Bp + (size_t)arow[i] * KD + dB + ac16[i] * 8);
            CP_COMMIT();
        }

        const uint32_t st = sb + stage * STAGE_M;
        #pragma unroll
        for (int ks = 0; ks < KC / 16; ++ks) {
            const uint32_t kcol = ks * 32 + colSel;
            uint32_t af[2][4];
            #pragma unroll
            for (int mt = 0; mt < 2; ++mt) {
                uint32_t off = SWZ128(aRowB + (uint32_t)(mt * 16 * 128) + kcol);
                LDSM_X4(af[mt][0], af[mt][1], af[mt][2], af[mt][3], st + OFF_A + off);
            }
            uint32_t bf[4][2];
            #pragma unroll
            for (int p = 0; p < 2; ++p) {
                uint32_t off = SWZ128(bRowB + (uint32_t)(p * 16 * 128) + kcol);
                uint32_t r0, r1, r2, r3;
                LDSM_X4(r0, r1, r2, r3, st + OFF_B_M + off);
                bf[2*p][0] = r0; bf[2*p][1] = r2;
                bf[2*p+1][0] = r1; bf[2*p+1][1] = r3;
            }
            #pragma unroll
            for (int mt = 0; mt < 2; ++mt)
                #pragma unroll
                for (int nt = 0; nt < 4; ++nt)
                    MMA_F16(acc[mt][nt], af[mt], bf[nt]);
        }
        if (++stage == NSTAGE) stage = 0;
    }

    float* slab = g_hidpart + (size_t)z * (Bn * Dn);
    const int gRow = lane >> 2;
    const int gCol = (lane & 3) * 2;
    #pragma unroll
    for (int mt = 0; mt < 2; ++mt)
        #pragma unroll
        for (int h2 = 0; h2 < 2; ++h2) {
            int row = rowBase + warpM * 32 + mt * 16 + h2 * 8 + gRow;
            #pragma unroll
            for (int nt = 0; nt < 4; ++nt) {
                int col = oBase + warpN * 32 + nt * 8 + gCol;
                float2 val = make_float2(acc[mt][nt][h2*2], acc[mt][nt][h2*2+1]);
                *(float2*)&slab[(size_t)row * Dn + col] = val;
            }
        }

    // ---- grid-wide completion, then fused logits (CTA flat-id = b-row) ----
    __threadfence();
    __syncthreads();
    if (tid == 0) {
        atomicAdd(&g_done, 1);
        while (atomicAdd(&g_done, 0) < GRID_M) __nanosleep(64);
    }
    __syncthreads();
    __threadfence();

    const int b = blockIdx.x + 16 * blockIdx.y + 32 * blockIdx.z;  // 0..255
    float a0 = 0.f, a1 = 0.f, a2 = 0.f;
    for (int d = tid; d < Dn; d += NTHREADS) {
        float hp = b1[d];
        #pragma unroll
        for (int zz = 0; zz < SPLITK; ++zz)
            hp += g_hidpart[(size_t)zz * (Bn*Dn) + b*Dn + d];
        hp = fmaxf(hp, 0.f);
        a0 = fmaf(hp, w2[        d], a0);
        a1 = fmaf(hp, w2[  Dn + d], a1);
        a2 = fmaf(hp, w2[2*Dn + d], a2);
    }
    float* red = (float*)smem;   // reuse dynamic smem
    float pv3[3] = {a0, a1, a2};
    #pragma unroll
    for (int i = 0; i < 3; ++i) {
        red[tid] = pv3[i]; __syncthreads();
        #pragma unroll
        for (int o = 128; o; o >>= 1) { if (tid < o) red[tid] += red[tid+o]; __syncthreads(); }
        if (!tid) out[b*NLn + i] = red[0] + b2[i];
        __syncthreads();
    }
}

extern "C" void kernel_launch(void* const* d_in, const int* in_sizes, int n_in,
                              void* d_out, int out_size) {
    const float* c_out  = (const float*)d_in[0];
    const float* e_emb  = (const float*)d_in[1];
    const int*   emask  = (const int*)  d_in[2];
    const float* W_c    = (const float*)d_in[3];
    const float* W_e    = (const float*)d_in[4];
    const float* v      = (const float*)d_in[5];
    const float* gate_w = (const float*)d_in[6];
    const float* gate_b = (const float*)d_in[7];
    const float* w1     = (const float*)d_in[8];
    const float* b1     = (const float*)d_in[9];
    const float* w2     = (const float*)d_in[10];
    const float* b2     = (const float*)d_in[11];
    float* out = (float*)d_out;

    cudaFuncSetAttribute(k_attn_mma, cudaFuncAttributeMaxDynamicSharedMemorySize, SMEM_TOTAL);
    cudaFuncSetAttribute(k_mlp1, cudaFuncAttributeMaxDynamicSharedMemorySize, SMEM_TOTAL_M);

    k_prep<<<NBLK_E + NBLK_W + NBLK_S, 256>>>(e_emb, W_e, W_c);
    k_attn_mma<<<dim3(NET, (Bn*Kn)/TCM, Hn), NTHREADS, SMEM_TOTAL>>>(c_out, v);
    k_fuse<<<Bn + NBLK_W1F, 512>>>(emask, c_out, gate_w, gate_b, w1, out);
    k_mlp1<<<dim3(Dn/TCN_M, Bn/TCM, SPLITK), NTHREADS, SMEM_TOTAL_M>>>(b1, w2, b2, out);
}

// round 16
// speedup vs baseline: 1.0219x; 1.0032x over previous
#include <cuda_runtime.h>
#include <cuda_fp16.h>
#include <math.h>
#include <stdint.h>

// Problem shapes
#define Bn  256
#define Kn  64
#define Dn  1024
#define KD  4096                // MLP1 K dim = 4*Dn
#define Hn  4
#define NLn 3

// Output layout in d_out (fp32): logits (B*NL), alpha (B*H*K), head_weights (B*H)
#define ALPHA_OFF 768
#define HW_OFF    (768 + Bn*Hn*Kn)

// HMMA GEMM tiling: CTA 128x128, warp tile 32x64, 8 warps, 2 CTAs/SM
#define TCM 128
#define TCN 128
#define KC  64                  // K elems per chunk (64 fp16 = 128B row)
#define NCHUNK (Dn / KC)        // 16
#define NET    (Dn / TCN)       // 8 e-tiles
#define NTHREADS 256
#define NSTAGE 3

// MLP1: CTA 128x64, split-k=8 -> 256 CTAs, 8-chunk pipeline
#define SPLITK 8
#define KSPAN  (KD / SPLITK)    // 512
#define NCHUNK_M (KSPAN / KC)   // 8
#define TCN_M 64

typedef unsigned long long u64;

// -------- scratch (static device globals; no allocation allowed) --------
__device__ float g_wcsum[Hn * Dn];
__device__ float g_upart[NET * Bn * Hn * Kn];       // 2 MB
__device__ float g_hidpart[SPLITK * Bn * Dn];       // 8 MB
// fp16 operands (single-rounded)
__device__ __half g_Ef[Bn * Kn * Dn];    // 32 MB
__device__ __half g_Wt[Hn * Dn * Dn];    // 8 MB  (transposed: [h][e][d])
__device__ __half g_w1h[Dn * KD];        // 8 MB  (w1 fp16, [N=1024][K=4096])
__device__ __half g_feath[Bn * KD];      // 2 MB  (features fp16, [256][4096])

// -------- helpers --------
__device__ __forceinline__ uint32_t smem_u32(const void* p) {
    uint32_t a;
    asm("{ .reg .u64 t; cvta.to.shared.u64 t, %1; cvt.u32.u64 %0, t; }" : "=r"(a) : "l"(p));
    return a;
}
__device__ __forceinline__ float tanhfast(float x) {
    float y; asm("tanh.approx.f32 %0, %1;" : "=f"(y) : "f"(x)); return y;
}
#define SWZ128(o) ((o) ^ (((o) >> 3) & 0x70))

__device__ __forceinline__ void cp16(uint32_t saddr, const void* gptr) {
    asm volatile("cp.async.cg.shared.global [%0], [%1], 16;"
                 :: "r"(saddr), "l"(__cvta_generic_to_global(gptr)) : "memory");
}
#define CP_COMMIT() asm volatile("cp.async.commit_group;" ::: "memory")
#define CP_WAIT(n)  asm volatile("cp.async.wait_group %0;" :: "n"(n) : "memory")

#define LDSM_X4(r0, r1, r2, r3, addr) \
    asm volatile("ldmatrix.sync.aligned.m8n8.x4.shared.b16 {%0,%1,%2,%3}, [%4];" \
                 : "=r"(r0), "=r"(r1), "=r"(r2), "=r"(r3) : "r"(addr))

#define MMA_F16(c, a, b) \
    asm volatile("mma.sync.aligned.m16n8k16.row.col.f32.f16.f16.f32 " \
                 "{%0,%1,%2,%3}, {%4,%5,%6,%7}, {%8,%9}, {%0,%1,%2,%3};" \
                 : "+f"((c)[0]), "+f"((c)[1]), "+f"((c)[2]), "+f"((c)[3]) \
                 : "r"((a)[0]), "r"((a)[1]), "r"((a)[2]), "r"((a)[3]), \
                   "r"((b)[0]), "r"((b)[1]))

// attn smem stage layout: A(16KB) + B(16KB) = 32KB per stage
#define OFF_A   0
#define OFF_B   16384
#define STAGE_BYTES 32768
#define SM_EXTRA (NSTAGE * STAGE_BYTES)
#define SMEM_TOTAL (NSTAGE * STAGE_BYTES + 4096)      // 102400 -> 2 CTAs/SM

// mlp1 smem stage layout: A(16KB) + B(8KB) = 24KB per stage
#define OFF_B_M  16384
#define STAGE_M  24576
#define SMEM_TOTAL_M (NSTAGE * STAGE_M)               // 73728 -> 2 CTAs/SM

// -------- K0: preprocessing (cvtE | cvtW | wcsum) ----
#define NBLK_E  (Bn*Kn*Dn/4/256)      // 16384
#define NBLK_W  ((Dn/32)*(Dn/32)*Hn)  // 4096
#define NBLK_S  (Hn*Dn*32/256)        // 512
__global__ void k_prep(const float* __restrict__ e, const float* __restrict__ W,
                       const float* __restrict__ W_c) {
    __shared__ float t[32][33];
    const int bx = blockIdx.x;
    const int tid = threadIdx.x;
    if (bx < NBLK_E) {
        size_t i = (size_t)bx * 256 + tid;   // over float4s
        float4 x = ((const float4*)e)[i];
        __half h0 = __float2half_rn(x.x), h1 = __float2half_rn(x.y);
        __half h2 = __float2half_rn(x.z), h3 = __float2half_rn(x.w);
        ((__half2*)g_Ef)[2*i    ] = __halves2half2(h0, h1);
        ((__half2*)g_Ef)[2*i + 1] = __halves2half2(h2, h3);
    } else if (bx < NBLK_E + NBLK_W) {
        const int b  = bx - NBLK_E;
        const int h  = b >> 10;
        const int dB = ((b & 1023) >> 5) * 32;
        const int eB = (b & 31) * 32;
        const int lx = tid & 31, ly = tid >> 5;  // 32 x 8
        #pragma unroll
        for (int r = 0; r < 4; ++r)
            t[ly + 8*r][lx] = W[((size_t)h*Dn + dB + ly + 8*r) * Dn + eB + lx];
        __syncthreads();
        #pragma unroll
        for (int r = 0; r < 4; ++r) {
            float x = t[lx][ly + 8*r];
            size_t oi = ((size_t)h*Dn + eB + ly + 8*r) * Dn + dB + lx;
            g_Wt[oi] = __float2half_rn(x);
        }
    } else {
        int warp = (((bx - NBLK_E - NBLK_W) << 8) + tid) >> 5;
        int lane = tid & 31;
        const float* p = W_c + (size_t)warp * Dn;
        float s = 0.f;
        #pragma unroll 8
        for (int j = lane; j < Dn; j += 32) s += p[j];
        #pragma unroll
        for (int o = 16; o; o >>= 1) s += __shfl_down_sync(0xffffffffu, s, o);
        if (!lane) g_wcsum[warp] = s;
    }
}

// -------- K2: HMMA fused  P = E @ Wt^T (fp16);  u = sum_e tanh(cp+P)*v ----
__global__ void __launch_bounds__(NTHREADS, 2)
k_attn_mma(const float* __restrict__ c_out, const float* __restrict__ v)
{
    extern __shared__ char smem[];
    const uint32_t sb = smem_u32(smem);
    const int tid   = threadIdx.x;
    const int wid   = tid >> 5;
    const int lane  = tid & 31;
    const int warpM = wid >> 1;
    const int warpN = wid & 1;

    const int et      = blockIdx.x;
    const int rowBase = blockIdx.y * TCM;
    const int h       = blockIdx.z;
    const int eBase   = et * TCN;

    const __half* Ap = g_Ef + (size_t)rowBase * Dn;
    const __half* Bp = g_Wt + ((size_t)h * Dn + eBase) * Dn;

    float* s_cce0 = (float*)(smem + SM_EXTRA);
    float* s_cce1 = s_cce0 + TCN;
    float* s_vv   = s_cce1 + TCN;
    float* s_red  = s_vv + TCN;

    const int b0 = rowBase >> 6;
    {
        int e0 = eBase + (tid & 127);
        float wc0 = g_wcsum[h * Dn + e0];
        if (tid < 128) {
            s_cce0[tid] = c_out[b0 * Dn + e0] * wc0;
            s_vv[tid]   = v[h * Dn + e0];
        } else {
            s_cce1[tid - 128] = c_out[(b0 + 1) * Dn + e0] * wc0;
        }
    }

    int arow[4], ac16[4]; uint32_t aso[4];
    #pragma unroll
    for (int i = 0; i < 4; ++i) {
        int seg = tid + i * NTHREADS;
        arow[i] = seg >> 3; ac16[i] = seg & 7;
        aso[i] = SWZ128((uint32_t)(arow[i] * 128 + ac16[i] * 16));
    }

    float acc[2][8][4];
    #pragma unroll
    for (int mt = 0; mt < 2; ++mt)
        #pragma unroll
        for (int nt = 0; nt < 8; ++nt)
            #pragma unroll
            for (int j = 0; j < 4; ++j) acc[mt][nt][j] = 0.f;

    const uint32_t aRowB = (uint32_t)((warpM * 32 + (lane & 15)) * 128);
    const uint32_t bRowB = (uint32_t)((warpN * 64 + (lane & 15)) * 128);
    const uint32_t colSel = (uint32_t)((lane >> 4) * 16);

    #pragma unroll
    for (int pc = 0; pc < 2; ++pc) {
        const uint32_t st = sb + pc * STAGE_BYTES;
        const int dB = pc * KC;
        #pragma unroll
        for (int i = 0; i < 4; ++i) {
            cp16(st + OFF_A + aso[i], Ap + (size_t)arow[i] * Dn + dB + ac16[i] * 8);
            cp16(st + OFF_B + aso[i], Bp + (size_t)arow[i] * Dn + dB + ac16[i] * 8);
        }
        CP_COMMIT();
    }

    int stage = 0;
    for (int c = 0; c < NCHUNK; ++c) {
        if (c + 2 < NCHUNK) { CP_WAIT(1); } else { CP_WAIT(0); }
        __syncthreads();

        if (c + 2 < NCHUNK) {
            int ns = stage + 2; if (ns >= NSTAGE) ns -= NSTAGE;
            const uint32_t stn = sb + ns * STAGE_BYTES;
            const int dB = (c + 2) * KC;
            #pragma unroll
            for (int i = 0; i < 4; ++i) {
                cp16(stn + OFF_A + aso[i], Ap + (size_t)arow[i] * Dn + dB + ac16[i] * 8);
                cp16(stn + OFF_B + aso[i], Bp + (size_t)arow[i] * Dn + dB + ac16[i] * 8);
            }
            CP_COMMIT();
        }

        const uint32_t st = sb + stage * STAGE_BYTES;
        #pragma unroll
        for (int ks = 0; ks < KC / 16; ++ks) {
            const uint32_t kcol = ks * 32 + colSel;
            uint32_t af[2][4];
            #pragma unroll
            for (int mt = 0; mt < 2; ++mt) {
                uint32_t off = SWZ128(aRowB + (uint32_t)(mt * 16 * 128) + kcol);
                LDSM_X4(af[mt][0], af[mt][1], af[mt][2], af[mt][3], st + OFF_A + off);
            }
            uint32_t bf[8][2];
            #pragma unroll
            for (int p = 0; p < 4; ++p) {
                uint32_t off = SWZ128(bRowB + (uint32_t)(p * 16 * 128) + kcol);
                uint32_t r0, r1, r2, r3;
                LDSM_X4(r0, r1, r2, r3, st + OFF_B + off);
                bf[2*p][0] = r0; bf[2*p][1] = r2;
                bf[2*p+1][0] = r1; bf[2*p+1][1] = r3;
            }
            #pragma unroll
            for (int mt = 0; mt < 2; ++mt)
                #pragma unroll
                for (int nt = 0; nt < 8; ++nt)
                    MMA_F16(acc[mt][nt], af[mt], bf[nt]);
        }
        if (++stage == NSTAGE) stage = 0;
    }

    const int gRow = lane >> 2;
    const int c2   = (lane & 3) * 2;
    const float* cce = (warpM >= 2) ? s_cce1 : s_cce0;

    #pragma unroll
    for (int mt = 0; mt < 2; ++mt) {
        #pragma unroll
        for (int h2 = 0; h2 < 2; ++h2) {
            float p = 0.f;
            #pragma unroll
            for (int nt = 0; nt < 8; ++nt) {
                int e0 = warpN * 64 + nt * 8 + c2;
                float v0 = acc[mt][nt][h2 * 2 + 0];
                float v1 = acc[mt][nt][h2 * 2 + 1];
                p += tanhfast(v0 + cce[e0    ]) * s_vv[e0    ];
                p += tanhfast(v1 + cce[e0 + 1]) * s_vv[e0 + 1];
            }
            p += __shfl_xor_sync(0xffffffffu, p, 1);
            p += __shfl_xor_sync(0xffffffffu, p, 2);
            if ((lane & 3) == 0) {
                int lrow2 = warpM * 32 + mt * 16 + h2 * 8 + gRow;
                s_red[lrow2 * 2 + warpN] = p;
            }
        }
    }
    __syncthreads();

    if (tid < 128) {
        float s = s_red[tid*2] + s_red[tid*2+1];
        int rg = rowBase + tid;
        int bb = rg >> 6, kk = rg & 63;
        g_upart[et * (Bn * Hn * Kn) + ((bb * Hn + h) << 6) + kk] = s;
    }
}

// -------- K4: FUSED softmax + e_att_heads + gate + head_wts + feat
//          PLUS w1 -> fp16 conversion on the extra blocks (bx >= Bn) ----
#define NBLK_W1F (Dn*KD/4/512)   // 2048 blocks of 512 threads over float4s
__global__ void __launch_bounds__(512)
k_fuse(const int* __restrict__ mask, const float* __restrict__ c_out,
       const float* __restrict__ gate_w, const float* __restrict__ gate_b,
       const float* __restrict__ w1, float* __restrict__ out)
{
    const int tid = threadIdx.x;
    if (blockIdx.x >= Bn) {
        // w1 -> fp16 copy (no barriers on this path); consumed by k_mlp1 later
        size_t i = (size_t)(blockIdx.x - Bn) * 512 + tid;
        float4 x = ((const float4*)w1)[i];
        __half h0 = __float2half_rn(x.x), h1 = __float2half_rn(x.y);
        __half h2 = __float2half_rn(x.z), h3 = __float2half_rn(x.w);
        ((__half2*)g_w1h)[2*i    ] = __halves2half2(h0, h1);
        ((__half2*)g_w1h)[2*i + 1] = __halves2half2(h2, h3);
        return;
    }
    const int b = blockIdx.x;
    const int lane = tid & 31, wid = tid >> 5;   // 16 warps

    __shared__ float red[256];
    __shared__ float sal[256];          // alpha [h][k]
    __shared__ float gred[16][5];
    __shared__ float shw[4];

    // ---- softmax over k within each h (4 groups of 64 threads) ----
    float s = 0.f;
    if (tid < 256) {
        const int hh = tid >> 6, kk = tid & 63;
        #pragma unroll
        for (int nt = 0; nt < NET; ++nt)
            s += g_upart[nt * (Bn*Hn*Kn) + ((b * Hn + hh) << 6) + kk];
        if (mask[b * Kn + kk] == 0) s = __int_as_float(0xff800000);
        red[tid] = s;
    }
    __syncthreads();
    #pragma unroll
    for (int o = 32; o; o >>= 1) {
        if (tid < 256 && (tid & 63) < o) red[tid] = fmaxf(red[tid], red[tid + o]);
        __syncthreads();
    }
    float ex = 0.f;
    if (tid < 256) ex = __expf(s - red[(tid >> 6) << 6]);
    __syncthreads();
    if (tid < 256) red[tid] = ex;
    __syncthreads();
    #pragma unroll
    for (int o = 32; o; o >>= 1) {
        if (tid < 256 && (tid & 63) < o) red[tid] += red[tid + o];
        __syncthreads();
    }
    if (tid < 256) {
        float al = ex / red[(tid >> 6) << 6];
        sal[tid] = al;
        out[ALPHA_OFF + b * (Hn*Kn) + tid] = al;
    }
    __syncthreads();

    // ---- e_att_heads for d-pair (half2 loads) ----
    const __half2* ep2 = (const __half2*)(g_Ef + (size_t)b * Kn * Dn) + tid;
    float2 A0 = {0.f, 0.f}, A1 = {0.f, 0.f}, A2 = {0.f, 0.f}, A3 = {0.f, 0.f};
    #pragma unroll 8
    for (int k = 0; k < Kn; ++k) {
        float2 ev = __half22float2(ep2[k * (Dn/2)]);
        float s0 = sal[k], s1 = sal[64+k], s2 = sal[128+k], s3 = sal[192+k];
        A0.x = fmaf(s0, ev.x, A0.x); A0.y = fmaf(s0, ev.y, A0.y);
        A1.x = fmaf(s1, ev.x, A1.x); A1.y = fmaf(s1, ev.y, A1.y);
        A2.x = fmaf(s2, ev.x, A2.x); A2.y = fmaf(s2, ev.y, A2.y);
        A3.x = fmaf(s3, ev.x, A3.x); A3.y = fmaf(s3, ev.y, A3.y);
    }

    // ---- gate: per-thread pair partials; warp + cross-warp reduce ----
    float2 cv  = ((const float2*)(c_out + (size_t)b * Dn))[tid];
    float2 gwc = ((const float2*)gate_w)[tid];
    float2 gwe = ((const float2*)(gate_w + Dn))[tid];
    float pv[5];
    pv[0] = cv.x * gwc.x + cv.y * gwc.y;
    pv[1] = A0.x * gwe.x + A0.y * gwe.y;
    pv[2] = A1.x * gwe.x + A1.y * gwe.y;
    pv[3] = A2.x * gwe.x + A2.y * gwe.y;
    pv[4] = A3.x * gwe.x + A3.y * gwe.y;
    #pragma unroll
    for (int i = 0; i < 5; ++i) {
        float x = pv[i];
        #pragma unroll
        for (int o = 16; o; o >>= 1) x += __shfl_xor_sync(0xffffffffu, x, o);
        if (!lane) gred[wid][i] = x;
    }
    __syncthreads();
    if (wid == 0) {
        #pragma unroll
        for (int i = 0; i < 5; ++i) {
            float x = (lane < 16) ? gred[lane][i] : 0.f;
            #pragma unroll
            for (int o = 8; o; o >>= 1) x += __shfl_xor_sync(0xffffffffu, x, o);
            if (!lane) gred[0][i] = x;
        }
        if (!lane) {
            float gb = gate_b[0];
            float g0 = gred[0][0] + gred[0][1] + gb, g1 = gred[0][0] + gred[0][2] + gb;
            float g2 = gred[0][0] + gred[0][3] + gb, g3 = gred[0][0] + gred[0][4] + gb;
            float mx = fmaxf(fmaxf(g0, g1), fmaxf(g2, g3));
            float e0 = __expf(g0 - mx), e1 = __expf(g1 - mx);
            float e2 = __expf(g2 - mx), e3 = __expf(g3 - mx);
            float inv = 1.f / (e0 + e1 + e2 + e3);
            shw[0] = e0*inv; shw[1] = e1*inv; shw[2] = e2*inv; shw[3] = e3*inv;
            out[HW_OFF + b*Hn + 0] = shw[0]; out[HW_OFF + b*Hn + 1] = shw[1];
            out[HW_OFF + b*Hn + 2] = shw[2]; out[HW_OFF + b*Hn + 3] = shw[3];
        }
    }
    __syncthreads();

    // ---- feature vector (fp16, half2 stores) ----
    float hw0 = shw[0], hw1 = shw[1], hw2 = shw[2], hw3 = shw[3];
    float2 ea;
    ea.x = hw0*A0.x + hw1*A1.x + hw2*A2.x + hw3*A3.x;
    ea.y = hw0*A0.y + hw1*A1.y + hw2*A2.y + hw3*A3.y;
    __half2* fb = (__half2*)(g_feath + (size_t)b * KD);
    fb[            tid] = __floats2half2_rn(cv.x, cv.y);
    fb[ (Dn/2)   + tid] = __floats2half2_rn(ea.x, ea.y);
    fb[2*(Dn/2)  + tid] = __floats2half2_rn(fabsf(cv.x - ea.x), fabsf(cv.y - ea.y));
    fb[3*(Dn/2)  + tid] = __floats2half2_rn(cv.x * ea.x, cv.y * ea.y);
}

// -------- K7: hid_part = feat @ w1.T via HMMA fp16 --------
// CTA 128(M) x 64(N), 8 warps (warp tile 32x32), split-k=8 -> 256 CTAs
__global__ void __launch_bounds__(NTHREADS, 2)
k_mlp1() {
    extern __shared__ char smem[];
    const uint32_t sb = smem_u32(smem);
    const int tid   = threadIdx.x;
    const int wid   = tid >> 5;
    const int lane  = tid & 31;
    const int warpM = wid >> 1;     // 0..3 (32 rows)
    const int warpN = wid & 1;      // 0..1 (32 cols)

    const int oBase   = blockIdx.x * TCN_M;
    const int rowBase = blockIdx.y * TCM;
    const int z       = blockIdx.z;
    const int kBase   = z * KSPAN;

    const __half* Ap = g_feath + (size_t)rowBase * KD + kBase;
    const __half* Bp = g_w1h   + (size_t)oBase * KD + kBase;

    int arow[4], ac16[4]; uint32_t aso[4];
    #pragma unroll
    for (int i = 0; i < 4; ++i) {
        int seg = tid + i * NTHREADS;
        arow[i] = seg >> 3; ac16[i] = seg & 7;
        aso[i] = SWZ128((uint32_t)(arow[i] * 128 + ac16[i] * 16));
    }

    float acc[2][4][4];
    #pragma unroll
    for (int mt = 0; mt < 2; ++mt)
        #pragma unroll
        for (int nt = 0; nt < 4; ++nt)
            #pragma unroll
            for (int j = 0; j < 4; ++j) acc[mt][nt][j] = 0.f;

    const uint32_t aRowB = (uint32_t)((warpM * 32 + (lane & 15)) * 128);
    const uint32_t bRowB = (uint32_t)((warpN * 32 + (lane & 15)) * 128);
    const uint32_t colSel = (uint32_t)((lane >> 4) * 16);

    #pragma unroll
    for (int pc = 0; pc < 2; ++pc) {
        const uint32_t st = sb + pc * STAGE_M;
        const int dB = pc * KC;
        #pragma unroll
        for (int i = 0; i < 4; ++i)
            cp16(st + OFF_A + aso[i], Ap + (size_t)arow[i] * KD + dB + ac16[i] * 8);
        #pragma unroll
        for (int i = 0; i < 2; ++i)
            cp16(st + OFF_B_M + aso[i], Bp + (size_t)arow[i] * KD + dB + ac16[i] * 8);
        CP_COMMIT();
    }

    int stage = 0;
    for (int c = 0; c < NCHUNK_M; ++c) {
        if (c + 2 < NCHUNK_M) { CP_WAIT(1); } else { CP_WAIT(0); }
        __syncthreads();

        if (c + 2 < NCHUNK_M) {
            int ns = stage + 2; if (ns >= NSTAGE) ns -= NSTAGE;
            const uint32_t stn = sb + ns * STAGE_M;
            const int dB = (c + 2) * KC;
            #pragma unroll
            for (int i = 0; i < 4; ++i)
                cp16(stn + OFF_A + aso[i], Ap + (size_t)arow[i] * KD + dB + ac16[i] * 8);
            #pragma unroll
            for (int i = 0; i < 2; ++i)
                cp16(stn + OFF_B_M + aso[i], Bp + (size_t)arow[i] * KD + dB + ac16[i] * 8);
            CP_COMMIT();
        }

        const uint32_t st = sb + stage * STAGE_M;
        #pragma unroll
        for (int ks = 0; ks < KC / 16; ++ks) {
            const uint32_t kcol = ks * 32 + colSel;
            uint32_t af[2][4];
            #pragma unroll
            for (int mt = 0; mt < 2; ++mt) {
                uint32_t off = SWZ128(aRowB + (uint32_t)(mt * 16 * 128) + kcol);
                LDSM_X4(af[mt][0], af[mt][1], af[mt][2], af[mt][3], st + OFF_A + off);
            }
            uint32_t bf[4][2];
            #pragma unroll
            for (int p = 0; p < 2; ++p) {
                uint32_t off = SWZ128(bRowB + (uint32_t)(p * 16 * 128) + kcol);
                uint32_t r0, r1, r2, r3;
                LDSM_X4(r0, r1, r2, r3, st + OFF_B_M + off);
                bf[2*p][0] = r0; bf[2*p][1] = r2;
                bf[2*p+1][0] = r1; bf[2*p+1][1] = r3;
            }
            #pragma unroll
            for (int mt = 0; mt < 2; ++mt)
                #pragma unroll
                for (int nt = 0; nt < 4; ++nt)
                    MMA_F16(acc[mt][nt], af[mt], bf[nt]);
        }
        if (++stage == NSTAGE) stage = 0;
    }

    float* slab = g_hidpart + (size_t)z * (Bn * Dn);
    const int gRow = lane >> 2;
    const int gCol = (lane & 3) * 2;
    #pragma unroll
    for (int mt = 0; mt < 2; ++mt)
        #pragma unroll
        for (int h2 = 0; h2 < 2; ++h2) {
            int row = rowBase + warpM * 32 + mt * 16 + h2 * 8 + gRow;
            #pragma unroll
            for (int nt = 0; nt < 4; ++nt) {
                int col = oBase + warpN * 32 + nt * 8 + gCol;
                float2 val = make_float2(acc[mt][nt][h2*2], acc[mt][nt][h2*2+1]);
                *(float2*)&slab[(size_t)row * Dn + col] = val;
            }
        }
}

// -------- K8: relu(sum hid_parts + b1) @ w2.T + b2 -> logits --------
__global__ void __launch_bounds__(256)
k_logits(const float* __restrict__ b1, const float* __restrict__ w2,
         const float* __restrict__ b2, float* __restrict__ out) {
    const int b = blockIdx.x, tid = threadIdx.x;
    float a0 = 0.f, a1 = 0.f, a2 = 0.f;
    // each thread owns 4 consecutive d (float4 slab loads)
    {
        const int d4 = tid;          // 0..255 -> d = d4*4
        float4 hp4 = ((const float4*)b1)[d4];
        #pragma unroll
        for (int zz = 0; zz < SPLITK; ++zz) {
            float4 p = ((const float4*)(g_hidpart + (size_t)zz * (Bn*Dn) + b*Dn))[d4];
            hp4.x += p.x; hp4.y += p.y; hp4.z += p.z; hp4.w += p.w;
        }
        hp4.x = fmaxf(hp4.x, 0.f); hp4.y = fmaxf(hp4.y, 0.f);
        hp4.z = fmaxf(hp4.z, 0.f); hp4.w = fmaxf(hp4.w, 0.f);
        float4 w0 = ((const float4*)w2)[d4];
        float4 w1v = ((const float4*)(w2 + Dn))[d4];
        float4 w2v = ((const float4*)(w2 + 2*Dn))[d4];
        a0 = hp4.x*w0.x + hp4.y*w0.y + hp4.z*w0.z + hp4.w*w0.w;
        a1 = hp4.x*w1v.x + hp4.y*w1v.y + hp4.z*w1v.z + hp4.w*w1v.w;
        a2 = hp4.x*w2v.x + hp4.y*w2v.y + hp4.z*w2v.z + hp4.w*w2v.w;
    }
    __shared__ float red[256];
    float pv[3] = {a0, a1, a2};
    #pragma unroll
    for (int i = 0; i < 3; ++i) {
        red[tid] = pv[i]; __syncthreads();
        #pragma unroll
        for (int o = 128; o; o >>= 1) { if (tid < o) red[tid] += red[tid+o]; __syncthreads(); }
        if (!tid) out[b*NLn + i] = red[0] + b2[i];
        __syncthreads();
    }
}

extern "C" void kernel_launch(void* const* d_in, const int* in_sizes, int n_in,
                              void* d_out, int out_size) {
    const float* c_out  = (const float*)d_in[0];
    const float* e_emb  = (const float*)d_in[1];
    const int*   emask  = (const int*)  d_in[2];
    const float* W_c    = (const float*)d_in[3];
    const float* W_e    = (const float*)d_in[4];
    const float* v      = (const float*)d_in[5];
    const float* gate_w = (const float*)d_in[6];
    const float* gate_b = (const float*)d_in[7];
    const float* w1     = (const float*)d_in[8];
    const float* b1     = (const float*)d_in[9];
    const float* w2     = (const float*)d_in[10];
    const float* b2     = (const float*)d_in[11];
    float* out = (float*)d_out;

    cudaFuncSetAttribute(k_attn_mma, cudaFuncAttributeMaxDynamicSharedMemorySize, SMEM_TOTAL);
    cudaFuncSetAttribute(k_mlp1, cudaFuncAttributeMaxDynamicSharedMemorySize, SMEM_TOTAL_M);

    k_prep<<<NBLK_E + NBLK_W + NBLK_S, 256>>>(e_emb, W_e, W_c);
    k_attn_mma<<<dim3(NET, (Bn*Kn)/TCM, Hn), NTHREADS, SMEM_TOTAL>>>(c_out, v);
    k_fuse<<<Bn + NBLK_W1F, 512>>>(emask, c_out, gate_w, gate_b, w1, out);
    k_mlp1<<<dim3(Dn/TCN_M, Bn/TCM, SPLITK), NTHREADS, SMEM_TOTAL_M>>>();
    k_logits<<<Bn, 256>>>(b1, w2, b2, out);
}

// round 17
// speedup vs baseline: 1.0242x; 1.0022x over previous
#include <cuda_runtime.h>
#include <cuda_fp16.h>
#include <math.h>
#include <stdint.h>

// Problem shapes
#define Bn  256
#define Kn  64
#define Dn  1024
#define KD  4096                // MLP1 K dim = 4*Dn
#define Hn  4
#define NLn 3

// Output layout in d_out (fp32): logits (B*NL), alpha (B*H*K), head_weights (B*H)
#define ALPHA_OFF 768
#define HW_OFF    (768 + Bn*Hn*Kn)

// HMMA GEMM tiling: CTA 128x128, warp tile 32x64, 8 warps, 2 CTAs/SM
#define TCM 128
#define TCN 128
#define KC  64                  // K elems per chunk (64 fp16 = 128B row)
#define NCHUNK (Dn / KC)        // 16
#define NET    (Dn / TCN)       // 8 e-tiles
#define NTHREADS 256
#define NSTAGE 3

// MLP1: CTA 128x64, split-k=8 -> 256 CTAs, 8-chunk pipeline
#define SPLITK 8
#define KSPAN  (KD / SPLITK)    // 512
#define NCHUNK_M (KSPAN / KC)   // 8
#define TCN_M 64

typedef unsigned long long u64;

// -------- scratch (static device globals; no allocation allowed) --------
__device__ float g_wcsum[Hn * Dn];
__device__ float g_upart[NET * Bn * Hn * Kn];       // 2 MB
__device__ float g_hidpart[SPLITK * Bn * Dn];       // 8 MB
// fp16 operands (single-rounded)
__device__ __half g_Ef[Bn * Kn * Dn];    // 32 MB
__device__ __half g_Wt[Hn * Dn * Dn];    // 8 MB  (transposed: [h][e][d])
__device__ __half g_w1h[Dn * KD];        // 8 MB  (w1 fp16, [N=1024][K=4096])
__device__ __half g_feath[Bn * KD];      // 2 MB  (features fp16, [256][4096])

// -------- helpers --------
__device__ __forceinline__ uint32_t smem_u32(const void* p) {
    uint32_t a;
    asm("{ .reg .u64 t; cvta.to.shared.u64 t, %1; cvt.u32.u64 %0, t; }" : "=r"(a) : "l"(p));
    return a;
}
__device__ __forceinline__ float tanhfast(float x) {
    float y; asm("tanh.approx.f32 %0, %1;" : "=f"(y) : "f"(x)); return y;
}
#define SWZ128(o) ((o) ^ (((o) >> 3) & 0x70))

__device__ __forceinline__ void cp16(uint32_t saddr, const void* gptr) {
    asm volatile("cp.async.cg.shared.global [%0], [%1], 16;"
                 :: "r"(saddr), "l"(__cvta_generic_to_global(gptr)) : "memory");
}
#define CP_COMMIT() asm volatile("cp.async.commit_group;" ::: "memory")
#define CP_WAIT(n)  asm volatile("cp.async.wait_group %0;" :: "n"(n) : "memory")

#define LDSM_X4(r0, r1, r2, r3, addr) \
    asm volatile("ldmatrix.sync.aligned.m8n8.x4.shared.b16 {%0,%1,%2,%3}, [%4];" \
                 : "=r"(r0), "=r"(r1), "=r"(r2), "=r"(r3) : "r"(addr))

#define MMA_F16(c, a, b) \
    asm volatile("mma.sync.aligned.m16n8k16.row.col.f32.f16.f16.f32 " \
                 "{%0,%1,%2,%3}, {%4,%5,%6,%7}, {%8,%9}, {%0,%1,%2,%3};" \
                 : "+f"((c)[0]), "+f"((c)[1]), "+f"((c)[2]), "+f"((c)[3]) \
                 : "r"((a)[0]), "r"((a)[1]), "r"((a)[2]), "r"((a)[3]), \
                   "r"((b)[0]), "r"((b)[1]))

// attn smem stage layout: A(16KB) + B(16KB) = 32KB per stage
#define OFF_A   0
#define OFF_B   16384
#define STAGE_BYTES 32768
#define SM_EXTRA (NSTAGE * STAGE_BYTES)
#define SMEM_TOTAL (NSTAGE * STAGE_BYTES + 4096)      // 102400 -> 2 CTAs/SM

// mlp1 smem stage layout: A(16KB) + B(8KB) = 24KB per stage
#define OFF_B_M  16384
#define STAGE_M  24576
#define SMEM_TOTAL_M (NSTAGE * STAGE_M)               // 73728 -> 2 CTAs/SM

// -------- K0: preprocessing (cvtE | cvtW | wcsum) ----
#define NBLK_E  (Bn*Kn*Dn/4/256)      // 16384
#define NBLK_W  ((Dn/32)*(Dn/32)*Hn)  // 4096
#define NBLK_S  (Hn*Dn*32/256)        // 512
__global__ void k_prep(const float* __restrict__ e, const float* __restrict__ W,
                       const float* __restrict__ W_c) {
    __shared__ float t[32][33];
    const int bx = blockIdx.x;
    const int tid = threadIdx.x;
    if (bx < NBLK_E) {
        size_t i = (size_t)bx * 256 + tid;   // over float4s
        float4 x = ((const float4*)e)[i];
        __half h0 = __float2half_rn(x.x), h1 = __float2half_rn(x.y);
        __half h2 = __float2half_rn(x.z), h3 = __float2half_rn(x.w);
        ((__half2*)g_Ef)[2*i    ] = __halves2half2(h0, h1);
        ((__half2*)g_Ef)[2*i + 1] = __halves2half2(h2, h3);
    } else if (bx < NBLK_E + NBLK_W) {
        const int b  = bx - NBLK_E;
        const int h  = b >> 10;
        const int dB = ((b & 1023) >> 5) * 32;
        const int eB = (b & 31) * 32;
        const int lx = tid & 31, ly = tid >> 5;  // 32 x 8
        #pragma unroll
        for (int r = 0; r < 4; ++r)
            t[ly + 8*r][lx] = W[((size_t)h*Dn + dB + ly + 8*r) * Dn + eB + lx];
        __syncthreads();
        #pragma unroll
        for (int r = 0; r < 4; ++r) {
            float x = t[lx][ly + 8*r];
            size_t oi = ((size_t)h*Dn + eB + ly + 8*r) * Dn + dB + lx;
            g_Wt[oi] = __float2half_rn(x);
        }
    } else {
        int warp = (((bx - NBLK_E - NBLK_W) << 8) + tid) >> 5;
        int lane = tid & 31;
        const float* p = W_c + (size_t)warp * Dn;
        float s = 0.f;
        #pragma unroll 8
        for (int j = lane; j < Dn; j += 32) s += p[j];
        #pragma unroll
        for (int o = 16; o; o >>= 1) s += __shfl_down_sync(0xffffffffu, s, o);
        if (!lane) g_wcsum[warp] = s;
    }
}

// -------- K2: HMMA fused  P = E @ Wt^T (fp16);  u = sum_e tanh(cp+P)*v ----
__global__ void __launch_bounds__(NTHREADS, 2)
k_attn_mma(const float* __restrict__ c_out, const float* __restrict__ v)
{
    extern __shared__ char smem[];
    const uint32_t sb = smem_u32(smem);
    const int tid   = threadIdx.x;
    const int wid   = tid >> 5;
    const int lane  = tid & 31;
    const int warpM = wid >> 1;
    const int warpN = wid & 1;

    const int et      = blockIdx.x;
    const int rowBase = blockIdx.y * TCM;
    const int h       = blockIdx.z;
    const int eBase   = et * TCN;

    const __half* Ap = g_Ef + (size_t)rowBase * Dn;
    const __half* Bp = g_Wt + ((size_t)h * Dn + eBase) * Dn;

    float* s_cce0 = (float*)(smem + SM_EXTRA);
    float* s_cce1 = s_cce0 + TCN;
    float* s_vv   = s_cce1 + TCN;
    float* s_red  = s_vv + TCN;

    const int b0 = rowBase >> 6;
    {
        int e0 = eBase + (tid & 127);
        float wc0 = g_wcsum[h * Dn + e0];
        if (tid < 128) {
            s_cce0[tid] = c_out[b0 * Dn + e0] * wc0;
            s_vv[tid]   = v[h * Dn + e0];
        } else {
            s_cce1[tid - 128] = c_out[(b0 + 1) * Dn + e0] * wc0;
        }
    }

    int arow[4], ac16[4]; uint32_t aso[4];
    #pragma unroll
    for (int i = 0; i < 4; ++i) {
        int seg = tid + i * NTHREADS;
        arow[i] = seg >> 3; ac16[i] = seg & 7;
        aso[i] = SWZ128((uint32_t)(arow[i] * 128 + ac16[i] * 16));
    }

    float acc[2][8][4];
    #pragma unroll
    for (int mt = 0; mt < 2; ++mt)
        #pragma unroll
        for (int nt = 0; nt < 8; ++nt)
            #pragma unroll
            for (int j = 0; j < 4; ++j) acc[mt][nt][j] = 0.f;

    const uint32_t aRowB = (uint32_t)((warpM * 32 + (lane & 15)) * 128);
    const uint32_t bRowB = (uint32_t)((warpN * 64 + (lane & 15)) * 128);
    const uint32_t colSel = (uint32_t)((lane >> 4) * 16);

    #pragma unroll
    for (int pc = 0; pc < 2; ++pc) {
        const uint32_t st = sb + pc * STAGE_BYTES;
        const int dB = pc * KC;
        #pragma unroll
        for (int i = 0; i < 4; ++i) {
            cp16(st + OFF_A + aso[i], Ap + (size_t)arow[i] * Dn + dB + ac16[i] * 8);
            cp16(st + OFF_B + aso[i], Bp + (size_t)arow[i] * Dn + dB + ac16[i] * 8);
        }
        CP_COMMIT();
    }

    int stage = 0;
    for (int c = 0; c < NCHUNK; ++c) {
        if (c + 2 < NCHUNK) { CP_WAIT(1); } else { CP_WAIT(0); }
        __syncthreads();

        if (c + 2 < NCHUNK) {
            int ns = stage + 2; if (ns >= NSTAGE) ns -= NSTAGE;
            const uint32_t stn = sb + ns * STAGE_BYTES;
            const int dB = (c + 2) * KC;
            #pragma unroll
            for (int i = 0; i < 4; ++i) {
                cp16(stn + OFF_A + aso[i], Ap + (size_t)arow[i] * Dn + dB + ac16[i] * 8);
                cp16(stn + OFF_B + aso[i], Bp + (size_t)arow[i] * Dn + dB + ac16[i] * 8);
            }
            CP_COMMIT();
        }

        const uint32_t st = sb + stage * STAGE_BYTES;
        #pragma unroll
        for (int ks = 0; ks < KC / 16; ++ks) {
            const uint32_t kcol = ks * 32 + colSel;
            uint32_t af[2][4];
            #pragma unroll
            for (int mt = 0; mt < 2; ++mt) {
                uint32_t off = SWZ128(aRowB + (uint32_t)(mt * 16 * 128) + kcol);
                LDSM_X4(af[mt][0], af[mt][1], af[mt][2], af[mt][3], st + OFF_A + off);
            }
            uint32_t bf[8][2];
            #pragma unroll
            for (int p = 0; p < 4; ++p) {
                uint32_t off = SWZ128(bRowB + (uint32_t)(p * 16 * 128) + kcol);
                uint32_t r0, r1, r2, r3;
                LDSM_X4(r0, r1, r2, r3, st + OFF_B + off);
                bf[2*p][0] = r0; bf[2*p][1] = r2;
                bf[2*p+1][0] = r1; bf[2*p+1][1] = r3;
            }
            #pragma unroll
            for (int mt = 0; mt < 2; ++mt)
                #pragma unroll
                for (int nt = 0; nt < 8; ++nt)
                    MMA_F16(acc[mt][nt], af[mt], bf[nt]);
        }
        if (++stage == NSTAGE) stage = 0;
    }

    const int gRow = lane >> 2;
    const int c2   = (lane & 3) * 2;
    const float* cce = (warpM >= 2) ? s_cce1 : s_cce0;

    #pragma unroll
    for (int mt = 0; mt < 2; ++mt) {
        #pragma unroll
        for (int h2 = 0; h2 < 2; ++h2) {
            float p = 0.f;
            #pragma unroll
            for (int nt = 0; nt < 8; ++nt) {
                int e0 = warpN * 64 + nt * 8 + c2;
                float v0 = acc[mt][nt][h2 * 2 + 0];
                float v1 = acc[mt][nt][h2 * 2 + 1];
                p += tanhfast(v0 + cce[e0    ]) * s_vv[e0    ];
                p += tanhfast(v1 + cce[e0 + 1]) * s_vv[e0 + 1];
            }
            p += __shfl_xor_sync(0xffffffffu, p, 1);
            p += __shfl_xor_sync(0xffffffffu, p, 2);
            if ((lane & 3) == 0) {
                int lrow2 = warpM * 32 + mt * 16 + h2 * 8 + gRow;
                s_red[lrow2 * 2 + warpN] = p;
            }
        }
    }
    __syncthreads();

    if (tid < 128) {
        float s = s_red[tid*2] + s_red[tid*2+1];
        int rg = rowBase + tid;
        int bb = rg >> 6, kk = rg & 63;
        g_upart[et * (Bn * Hn * Kn) + ((bb * Hn + h) << 6) + kk] = s;
    }
}

// -------- K4: FUSED softmax + e_att_heads + gate + head_wts + feat
//          PLUS w1 -> fp16 conversion on the extra blocks (bx >= Bn) ----
#define NBLK_W1F (Dn*KD/4/512)   // 2048 blocks of 512 threads over float4s
__global__ void __launch_bounds__(512)
k_fuse(const int* __restrict__ mask, const float* __restrict__ c_out,
       const float* __restrict__ gate_w, const float* __restrict__ gate_b,
       const float* __restrict__ w1, float* __restrict__ out)
{
    const int tid = threadIdx.x;
    if (blockIdx.x >= Bn) {
        // w1 -> fp16 copy (no barriers on this path); consumed by k_mlp1 later
        size_t i = (size_t)(blockIdx.x - Bn) * 512 + tid;
        float4 x = ((const float4*)w1)[i];
        __half h0 = __float2half_rn(x.x), h1 = __float2half_rn(x.y);
        __half h2 = __float2half_rn(x.z), h3 = __float2half_rn(x.w);
        ((__half2*)g_w1h)[2*i    ] = __halves2half2(h0, h1);
        ((__half2*)g_w1h)[2*i + 1] = __halves2half2(h2, h3);
        return;
    }
    const int b = blockIdx.x;
    const int lane = tid & 31, wid = tid >> 5;   // 16 warps

    __shared__ float pairmx[8];         // per-warp max (warps 0..7)
    __shared__ float pairsm[8];         // per-warp sum
    __shared__ float sal[256];          // alpha [h][k]
    __shared__ float gred[16][5];
    __shared__ float shw[4];

    // ---- softmax over k within each h: h-group = 2 warps (warps 0..7) ----
    // warp w handles (h = w>>1, k-half = (w&1)*32 + lane)
    float s = 0.f;
    if (wid < 8) {
        const int hh = wid >> 1, kk = (wid & 1) * 32 + lane;
        #pragma unroll
        for (int nt = 0; nt < NET; ++nt)
            s += g_upart[nt * (Bn*Hn*Kn) + ((b * Hn + hh) << 6) + kk];
        if (mask[b * Kn + kk] == 0) s = __int_as_float(0xff800000);
        float m = s;
        #pragma unroll
        for (int o = 16; o; o >>= 1) m = fmaxf(m, __shfl_xor_sync(0xffffffffu, m, o));
        if (!lane) pairmx[wid] = m;
    }
    __syncthreads();
    float ex = 0.f;
    if (wid < 8) {
        const int hh = wid >> 1;
        float mx = fmaxf(pairmx[hh*2], pairmx[hh*2+1]);
        ex = __expf(s - mx);
        float sm = ex;
        #pragma unroll
        for (int o = 16; o; o >>= 1) sm += __shfl_xor_sync(0xffffffffu, sm, o);
        if (!lane) pairsm[wid] = sm;
    }
    __syncthreads();
    if (wid < 8) {
        const int hh = wid >> 1, kk = (wid & 1) * 32 + lane;
        float al = ex / (pairsm[hh*2] + pairsm[hh*2+1]);
        sal[hh * 64 + kk] = al;
        out[ALPHA_OFF + b * (Hn*Kn) + hh * 64 + kk] = al;
    }
    __syncthreads();

    // ---- e_att_heads for d-pair (half2 loads) ----
    const __half2* ep2 = (const __half2*)(g_Ef + (size_t)b * Kn * Dn) + tid;
    float2 A0 = {0.f, 0.f}, A1 = {0.f, 0.f}, A2 = {0.f, 0.f}, A3 = {0.f, 0.f};
    #pragma unroll 8
    for (int k = 0; k < Kn; ++k) {
        float2 ev = __half22float2(ep2[k * (Dn/2)]);
        float s0 = sal[k], s1 = sal[64+k], s2 = sal[128+k], s3 = sal[192+k];
        A0.x = fmaf(s0, ev.x, A0.x); A0.y = fmaf(s0, ev.y, A0.y);
        A1.x = fmaf(s1, ev.x, A1.x); A1.y = fmaf(s1, ev.y, A1.y);
        A2.x = fmaf(s2, ev.x, A2.x); A2.y = fmaf(s2, ev.y, A2.y);
        A3.x = fmaf(s3, ev.x, A3.x); A3.y = fmaf(s3, ev.y, A3.y);
    }

    // ---- gate: per-thread pair partials; warp + cross-warp reduce ----
    float2 cv  = ((const float2*)(c_out + (size_t)b * Dn))[tid];
    float2 gwc = ((const float2*)gate_w)[tid];
    float2 gwe = ((const float2*)(gate_w + Dn))[tid];
    float pv[5];
    pv[0] = cv.x * gwc.x + cv.y * gwc.y;
    pv[1] = A0.x * gwe.x + A0.y * gwe.y;
    pv[2] = A1.x * gwe.x + A1.y * gwe.y;
    pv[3] = A2.x * gwe.x + A2.y * gwe.y;
    pv[4] = A3.x * gwe.x + A3.y * gwe.y;
    #pragma unroll
    for (int i = 0; i < 5; ++i) {
        float x = pv[i];
        #pragma unroll
        for (int o = 16; o; o >>= 1) x += __shfl_xor_sync(0xffffffffu, x, o);
        if (!lane) gred[wid][i] = x;
    }
    __syncthreads();
    if (wid == 0) {
        #pragma unroll
        for (int i = 0; i < 5; ++i) {
            float x = (lane < 16) ? gred[lane][i] : 0.f;
            #pragma unroll
            for (int o = 8; o; o >>= 1) x += __shfl_xor_sync(0xffffffffu, x, o);
            if (!lane) gred[0][i] = x;
        }
        if (!lane) {
            float gb = gate_b[0];
            float g0 = gred[0][0] + gred[0][1] + gb, g1 = gred[0][0] + gred[0][2] + gb;
            float g2 = gred[0][0] + gred[0][3] + gb, g3 = gred[0][0] + gred[0][4] + gb;
            float mx = fmaxf(fmaxf(g0, g1), fmaxf(g2, g3));
            float e0 = __expf(g0 - mx), e1 = __expf(g1 - mx);
            float e2 = __expf(g2 - mx), e3 = __expf(g3 - mx);
            float inv = 1.f / (e0 + e1 + e2 + e3);
            shw[0] = e0*inv; shw[1] = e1*inv; shw[2] = e2*inv; shw[3] = e3*inv;
            out[HW_OFF + b*Hn + 0] = shw[0]; out[HW_OFF + b*Hn + 1] = shw[1];
            out[HW_OFF + b*Hn + 2] = shw[2]; out[HW_OFF + b*Hn + 3] = shw[3];
        }
    }
    __syncthreads();

    // ---- feature vector (fp16, half2 stores) ----
    float hw0 = shw[0], hw1 = shw[1], hw2 = shw[2], hw3 = shw[3];
    float2 ea;
    ea.x = hw0*A0.x + hw1*A1.x + hw2*A2.x + hw3*A3.x;
    ea.y = hw0*A0.y + hw1*A1.y + hw2*A2.y + hw3*A3.y;
    __half2* fb = (__half2*)(g_feath + (size_t)b * KD);
    fb[            tid] = __floats2half2_rn(cv.x, cv.y);
    fb[ (Dn/2)   + tid] = __floats2half2_rn(ea.x, ea.y);
    fb[2*(Dn/2)  + tid] = __floats2half2_rn(fabsf(cv.x - ea.x), fabsf(cv.y - ea.y));
    fb[3*(Dn/2)  + tid] = __floats2half2_rn(cv.x * ea.x, cv.y * ea.y);
}

// -------- K7: hid_part = feat @ w1.T via HMMA fp16 --------
// CTA 128(M) x 64(N), 8 warps (warp tile 32x32), split-k=8 -> 256 CTAs
__global__ void __launch_bounds__(NTHREADS, 2)
k_mlp1() {
    extern __shared__ char smem[];
    const uint32_t sb = smem_u32(smem);
    const int tid   = threadIdx.x;
    const int wid   = tid >> 5;
    const int lane  = tid & 31;
    const int warpM = wid >> 1;     // 0..3 (32 rows)
    const int warpN = wid & 1;      // 0..1 (32 cols)

    const int oBase   = blockIdx.x * TCN_M;
    const int rowBase = blockIdx.y * TCM;
    const int z       = blockIdx.z;
    const int kBase   = z * KSPAN;

    const __half* Ap = g_feath + (size_t)rowBase * KD + kBase;
    const __half* Bp = g_w1h   + (size_t)oBase * KD + kBase;

    int arow[4], ac16[4]; uint32_t aso[4];
    #pragma unroll
    for (int i = 0; i < 4; ++i) {
        int seg = tid + i * NTHREADS;
        arow[i] = seg >> 3; ac16[i] = seg & 7;
        aso[i] = SWZ128((uint32_t)(arow[i] * 128 + ac16[i] * 16));
    }

    float acc[2][4][4];
    #pragma unroll
    for (int mt = 0; mt < 2; ++mt)
        #pragma unroll
        for (int nt = 0; nt < 4; ++nt)
            #pragma unroll
            for (int j = 0; j < 4; ++j) acc[mt][nt][j] = 0.f;

    const uint32_t aRowB = (uint32_t)((warpM * 32 + (lane & 15)) * 128);
    const uint32_t bRowB = (uint32_t)((warpN * 32 + (lane & 15)) * 128);
    const uint32_t colSel = (uint32_t)((lane >> 4) * 16);

    #pragma unroll
    for (int pc = 0; pc < 2; ++pc) {
        const uint32_t st = sb + pc * STAGE_M;
        const int dB = pc * KC;
        #pragma unroll
        for (int i = 0; i < 4; ++i)
            cp16(st + OFF_A + aso[i], Ap + (size_t)arow[i] * KD + dB + ac16[i] * 8);
        #pragma unroll
        for (int i = 0; i < 2; ++i)
            cp16(st + OFF_B_M + aso[i], Bp + (size_t)arow[i] * KD + dB + ac16[i] * 8);
        CP_COMMIT();
    }

    int stage = 0;
    for (int c = 0; c < NCHUNK_M; ++c) {
        if (c + 2 < NCHUNK_M) { CP_WAIT(1); } else { CP_WAIT(0); }
        __syncthreads();

        if (c + 2 < NCHUNK_M) {
            int ns = stage + 2; if (ns >= NSTAGE) ns -= NSTAGE;
            const uint32_t stn = sb + ns * STAGE_M;
            const int dB = (c + 2) * KC;
            #pragma unroll
            for (int i = 0; i < 4; ++i)
                cp16(stn + OFF_A + aso[i], Ap + (size_t)arow[i] * KD + dB + ac16[i] * 8);
            #pragma unroll
            for (int i = 0; i < 2; ++i)
                cp16(stn + OFF_B_M + aso[i], Bp + (size_t)arow[i] * KD + dB + ac16[i] * 8);
            CP_COMMIT();
        }

        const uint32_t st = sb + stage * STAGE_M;
        #pragma unroll
        for (int ks = 0; ks < KC / 16; ++ks) {
            const uint32_t kcol = ks * 32 + colSel;
            uint32_t af[2][4];
            #pragma unroll
            for (int mt = 0; mt < 2; ++mt) {
                uint32_t off = SWZ128(aRowB + (uint32_t)(mt * 16 * 128) + kcol);
                LDSM_X4(af[mt][0], af[mt][1], af[mt][2], af[mt][3], st + OFF_A + off);
            }
            uint32_t bf[4][2];
            #pragma unroll
            for (int p = 0; p < 2; ++p) {
                uint32_t off = SWZ128(bRowB + (uint32_t)(p * 16 * 128) + kcol);
                uint32_t r0, r1, r2, r3;
                LDSM_X4(r0, r1, r2, r3, st + OFF_B_M + off);
                bf[2*p][0] = r0; bf[2*p][1] = r2;
                bf[2*p+1][0] = r1; bf[2*p+1][1] = r3;
            }
            #pragma unroll
            for (int mt = 0; mt < 2; ++mt)
                #pragma unroll
                for (int nt = 0; nt < 4; ++nt)
                    MMA_F16(acc[mt][nt], af[mt], bf[nt]);
        }
        if (++stage == NSTAGE) stage = 0;
    }

    float* slab = g_hidpart + (size_t)z * (Bn * Dn);
    const int gRow = lane >> 2;
    const int gCol = (lane & 3) * 2;
    #pragma unroll
    for (int mt = 0; mt < 2; ++mt)
        #pragma unroll
        for (int h2 = 0; h2 < 2; ++h2) {
            int row = rowBase + warpM * 32 + mt * 16 + h2 * 8 + gRow;
            #pragma unroll
            for (int nt = 0; nt < 4; ++nt) {
                int col = oBase + warpN * 32 + nt * 8 + gCol;
                float2 val = make_float2(acc[mt][nt][h2*2], acc[mt][nt][h2*2+1]);
                *(float2*)&slab[(size_t)row * Dn + col] = val;
            }
        }
}

// -------- K8: relu(sum hid_parts + b1) @ w2.T + b2 -> logits --------
__global__ void __launch_bounds__(256)
k_logits(const float* __restrict__ b1, const float* __restrict__ w2,
         const float* __restrict__ b2, float* __restrict__ out) {
    const int b = blockIdx.x, tid = threadIdx.x;
    const int lane = tid & 31, wid = tid >> 5;
    float a0 = 0.f, a1 = 0.f, a2 = 0.f;
    {
        const int d4 = tid;          // 0..255 -> d = d4*4 (float4 slab loads)
        float4 hp4 = ((const float4*)b1)[d4];
        #pragma unroll
        for (int zz = 0; zz < SPLITK; ++zz) {
            float4 p = ((const float4*)(g_hidpart + (size_t)zz * (Bn*Dn) + b*Dn))[d4];
            hp4.x += p.x; hp4.y += p.y; hp4.z += p.z; hp4.w += p.w;
        }
        hp4.x = fmaxf(hp4.x, 0.f); hp4.y = fmaxf(hp4.y, 0.f);
        hp4.z = fmaxf(hp4.z, 0.f); hp4.w = fmaxf(hp4.w, 0.f);
        float4 w0 = ((const float4*)w2)[d4];
        float4 w1v = ((const float4*)(w2 + Dn))[d4];
        float4 w2v = ((const float4*)(w2 + 2*Dn))[d4];
        a0 = hp4.x*w0.x + hp4.y*w0.y + hp4.z*w0.z + hp4.w*w0.w;
        a1 = hp4.x*w1v.x + hp4.y*w1v.y + hp4.z*w1v.z + hp4.w*w1v.w;
        a2 = hp4.x*w2v.x + hp4.y*w2v.y + hp4.z*w2v.z + hp4.w*w2v.w;
    }
    // single-pass: warp-reduce all 3, one smem combine
    __shared__ float red[8][3];
    #pragma unroll
    for (int o = 16; o; o >>= 1) {
        a0 += __shfl_xor_sync(0xffffffffu, a0, o);
        a1 += __shfl_xor_sync(0xffffffffu, a1, o);
        a2 += __shfl_xor_sync(0xffffffffu, a2, o);
    }
    if (!lane) { red[wid][0] = a0; red[wid][1] = a1; red[wid][2] = a2; }
    __syncthreads();
    if (wid == 0 && lane < 3) {
        float s = 0.f;
        #pragma unroll
        for (int w = 0; w < 8; ++w) s += red[w][lane];
        out[b*NLn + lane] = s + b2[lane];
    }
}

extern "C" void kernel_launch(void* const* d_in, const int* in_sizes, int n_in,
                              void* d_out, int out_size) {
    const float* c_out  = (const float*)d_in[0];
    const float* e_emb  = (const float*)d_in[1];
    const int*   emask  = (const int*)  d_in[2];
    const float* W_c    = (const float*)d_in[3];
    const float* W_e    = (const float*)d_in[4];
    const float* v      = (const float*)d_in[5];
    const float* gate_w = (const float*)d_in[6];
    const float* gate_b = (const float*)d_in[7];
    const float* w1     = (const float*)d_in[8];
    const float* b1     = (const float*)d_in[9];
    const float* w2     = (const float*)d_in[10];
    const float* b2     = (const float*)d_in[11];
    float* out = (float*)d_out;

    cudaFuncSetAttribute(k_attn_mma, cudaFuncAttributeMaxDynamicSharedMemorySize, SMEM_TOTAL);
    cudaFuncSetAttribute(k_mlp1, cudaFuncAttributeMaxDynamicSharedMemorySize, SMEM_TOTAL_M);

    k_prep<<<NBLK_E + NBLK_W + NBLK_S, 256>>>(e_emb, W_e, W_c);
    k_attn_mma<<<dim3(NET, (Bn*Kn)/TCM, Hn), NTHREADS, SMEM_TOTAL>>>(c_out, v);
    k_fuse<<<Bn + NBLK_W1F, 512>>>(emask, c_out, gate_w, gate_b, w1, out);
    k_mlp1<<<dim3(Dn/TCN_M, Bn/TCM, SPLITK), NTHREADS, SMEM_TOTAL_M>>>();
    k_logits<<<Bn, 256>>>(b1, w2, b2, out);
}